// round 14
// baseline (speedup 1.0000x reference)
#include <cuda_runtime.h>
#include <cuda_fp16.h>
#include <math.h>
#include <stdint.h>

// Problem shape (fixed by the dataset)
#define BB   2
#define NN   1024
#define LLEN 4096
#define CDIM 1024
#define HH   16
#define DD   64

// ---------------- scratch (device globals; no allocs allowed) ---------------
__device__ __half g_xh[BB * NN * CDIM],   g_xl[BB * NN * CDIM];
__device__ __half g_y1[BB * LLEN * CDIM];                  // single fp16
__device__ __half g_w[4 * CDIM * CDIM];                    // single fp16 weights
__device__ __half g_qh[BB * NN * CDIM],   g_ql[BB * NN * CDIM];   // pre-scaled 0.125*log2e
__device__ __half g_k1[BB * LLEN * CDIM];                  // single fp16
__device__ __half g_v1[BB * LLEN * CDIM];                  // single fp16
__device__ __half g_ao[BB * NN * CDIM];                    // single fp16
__device__ float  g_po[2][BB * NN * CDIM];                 // split-K partials

extern __shared__ char dsm[];

// ---------------------------------------------------------------------------
// helpers
// ---------------------------------------------------------------------------
static __device__ __forceinline__ uint32_t smem_u32(const void* p) {
    uint32_t a;
    asm("{ .reg .u64 t; cvta.to.shared.u64 t, %1; cvt.u32.u64 %0, t; }"
        : "=r"(a) : "l"(p));
    return a;
}
static __device__ __forceinline__ void cp16(uint32_t dst, const void* src) {
    asm volatile("cp.async.cg.shared.global [%0], [%1], 16;"
                 :: "r"(dst), "l"(src));
}
static __device__ __forceinline__ void cp_commit() {
    asm volatile("cp.async.commit_group;" ::: "memory");
}
template <int N_>
static __device__ __forceinline__ void cp_wait() {
    asm volatile("cp.async.wait_group %0;" :: "n"(N_) : "memory");
}
static __device__ __forceinline__ void mma_f16(
    float* c, uint32_t a0, uint32_t a1, uint32_t a2, uint32_t a3,
    uint32_t b0, uint32_t b1)
{
    asm volatile(
        "mma.sync.aligned.m16n8k16.row.col.f32.f16.f16.f32 "
        "{%0,%1,%2,%3}, {%4,%5,%6,%7}, {%8,%9}, {%0,%1,%2,%3};"
        : "+f"(c[0]), "+f"(c[1]), "+f"(c[2]), "+f"(c[3])
        : "r"(a0), "r"(a1), "r"(a2), "r"(a3), "r"(b0), "r"(b1));
}
static __device__ __forceinline__ void ldsm_x4(uint32_t* r, uint32_t addr) {
    asm volatile("ldmatrix.sync.aligned.m8n8.x4.shared.b16 {%0,%1,%2,%3}, [%4];"
                 : "=r"(r[0]), "=r"(r[1]), "=r"(r[2]), "=r"(r[3]) : "r"(addr));
}
static __device__ __forceinline__ void ldsm_x2_t(uint32_t& r0, uint32_t& r1, uint32_t addr) {
    asm volatile("ldmatrix.sync.aligned.m8n8.x2.trans.shared.b16 {%0,%1}, [%2];"
                 : "=r"(r0), "=r"(r1) : "r"(addr));
}
static __device__ __forceinline__ void pack_hl16(
    float a, float b, uint32_t& hi, uint32_t& lo)
{
    __half2 h = __floats2half2_rn(a, b);
    __half2 l = __floats2half2_rn(a - __half2float(__low2half(h)),
                                  b - __half2float(__high2half(h)));
    hi = *(uint32_t*)&h;
    lo = *(uint32_t*)&l;
}

// ---------------------------------------------------------------------------
// fused convert: x -> fp16 hi/lo;  y, Wq..Wp -> single fp16.  ONE launch.
// ---------------------------------------------------------------------------
#define X4 ((BB * NN * CDIM) / 4)
#define Y4 ((BB * LLEN * CDIM) / 4)
#define W4 ((CDIM * CDIM) / 4)
#define TOT4 (X4 + Y4 + 4 * W4)

__global__ void convert_all(const float* __restrict__ x, const float* __restrict__ y,
                            const float* __restrict__ Wq, const float* __restrict__ Wk,
                            const float* __restrict__ Wv, const float* __restrict__ Wp,
                            __half* __restrict__ xh, __half* __restrict__ xl,
                            __half* __restrict__ y1, __half* __restrict__ w)
{
    const int i = blockIdx.x * blockDim.x + threadIdx.x;
    if (i >= TOT4) return;

    if (i < X4) {        // hi/lo split for x
        float4 v = ((const float4*)x)[i];
        uint32_t h0, l0, h1, l1;
        pack_hl16(v.x, v.y, h0, l0);
        pack_hl16(v.z, v.w, h1, l1);
        ((uint32_t*)xh)[i * 2 + 0] = h0;
        ((uint32_t*)xh)[i * 2 + 1] = h1;
        ((uint32_t*)xl)[i * 2 + 0] = l0;
        ((uint32_t*)xl)[i * 2 + 1] = l1;
    } else {             // single fp16 for y and weights
        const float* src; __half* dst; int j;
        int r = i - X4;
        if (r < Y4) { src = y; dst = y1; j = r; }
        else {
            r -= Y4;
            const int wsel = r / W4;
            j = r - wsel * W4;
            src = (wsel == 0) ? Wq : (wsel == 1) ? Wk : (wsel == 2) ? Wv : Wp;
            dst = w + (size_t)wsel * CDIM * CDIM;
        }
        float4 v = ((const float4*)src)[j];
        __half2 a = __floats2half2_rn(v.x, v.y);
        __half2 b = __floats2half2_rn(v.z, v.w);
        ((uint32_t*)dst)[j * 2 + 0] = *(uint32_t*)&a;
        ((uint32_t*)dst)[j * 2 + 1] = *(uint32_t*)&b;
    }
}

// ---------------------------------------------------------------------------
// GEMM body, fp16.  TWOA: C = (Ah+Al)*B^T, else C = Ah*B^T.
// BK=64, tile 128x128, 256 thr.  Smem row 128B, swizzle s^(r&7).
// omode: 0 = fp32 C, 1 = fp16 hi/lo (*oscale), 2 = fp16 single.
// ---------------------------------------------------------------------------
#define GTILE  16384
#define GEMM_SMEM (2 * 3 * GTILE)      // worst case (TWOA): 98304

#define LOAD_STAGE(cc, buf) do {                                              \
        const uint32_t bo = (uint32_t)(buf) * STB;                            \
        _Pragma("unroll")                                                     \
        for (int k = 0; k < 4; k++) {                                         \
            const int j   = tid + k * 256;                                    \
            const int row = j >> 3;                                           \
            const int s   = j & 7;                                            \
            const uint32_t doff = (uint32_t)(row * 128 + (((s) ^ (row & 7)) << 4)); \
            cp16(sb + bo + doff, Ah + (size_t)(m0 + row) * K + (cc) * 64 + s * 8); \
            if (TWOA)                                                         \
                cp16(sb + bo + GTILE + doff, Al + (size_t)(m0 + row) * K + (cc) * 64 + s * 8); \
            cp16(sb + bo + BOF + doff, Bs + (size_t)(n0 + row) * K + (cc) * 64 + s * 8); \
        }                                                                     \
    } while (0)

template <bool TWOA>
static __device__ __forceinline__ void gemm_body(
    float* __restrict__ C,
    __half* __restrict__ Ch, __half* __restrict__ Cl, __half* __restrict__ Cs,
    const __half* __restrict__ Ah, const __half* __restrict__ Al,
    const __half* __restrict__ Bs,
    float oscale, int omode, int N, int K, int bx, int by, int c0, int c1)
{
    constexpr uint32_t STB = TWOA ? 3 * GTILE : 2 * GTILE;
    constexpr uint32_t BOF = TWOA ? 2 * GTILE : GTILE;

    const int tid  = threadIdx.x;
    const int wid  = tid >> 5;
    const int lane = tid & 31;
    const int wm   = wid & 3;
    const int wn   = wid >> 2;
    const int g    = lane >> 2;
    const int t4   = lane & 3;
    const int m0   = by * 128;
    const int n0   = bx * 128;
    const int r15  = lane & 15;
    const int hi8  = lane >> 4;
    const int r7   = r15 & 7;

    const uint32_t sb = smem_u32(dsm);

    float acc[2][8][4];
#pragma unroll
    for (int mf = 0; mf < 2; mf++)
#pragma unroll
        for (int nf = 0; nf < 8; nf++)
#pragma unroll
            for (int j = 0; j < 4; j++) acc[mf][nf][j] = 0.0f;

    LOAD_STAGE(c0, 0);
    cp_commit();

    for (int c = c0; c < c1; c++) {
        const int buf = (c - c0) & 1;
        if (c + 1 < c1) {
            LOAD_STAGE(c + 1, buf ^ 1);
            cp_commit();
            cp_wait<1>();
        } else {
            cp_wait<0>();
        }
        __syncthreads();

        const uint32_t stg = sb + (uint32_t)buf * STB;

#pragma unroll
        for (int ks = 0; ks < 4; ks++) {
            const uint32_t sx = (uint32_t)((((2 * ks + hi8) ^ r7)) << 4);
            uint32_t ah[2][4], al[2][4];
#pragma unroll
            for (int mf = 0; mf < 2; mf++) {
                const uint32_t ra = (uint32_t)((wm * 32 + mf * 16 + r15) * 128) + sx;
                ldsm_x4(ah[mf], stg + ra);
                if (TWOA) ldsm_x4(al[mf], stg + GTILE + ra);
            }
#pragma unroll
            for (int nfp = 0; nfp < 4; nfp++) {
                uint32_t b4[4];
                ldsm_x4(b4, stg + BOF +
                        (uint32_t)((wn * 64 + nfp * 16 + r15) * 128) + sx);
#pragma unroll
                for (int mf = 0; mf < 2; mf++) {
                    float* cc0 = acc[mf][2 * nfp];
                    float* cc1 = acc[mf][2 * nfp + 1];
                    mma_f16(cc0, ah[mf][0], ah[mf][1], ah[mf][2], ah[mf][3], b4[0], b4[2]);
                    mma_f16(cc1, ah[mf][0], ah[mf][1], ah[mf][2], ah[mf][3], b4[1], b4[3]);
                    if (TWOA) {
                        mma_f16(cc0, al[mf][0], al[mf][1], al[mf][2], al[mf][3], b4[0], b4[2]);
                        mma_f16(cc1, al[mf][0], al[mf][1], al[mf][2], al[mf][3], b4[1], b4[3]);
                    }
                }
            }
        }
        __syncthreads();
    }

#pragma unroll
    for (int mf = 0; mf < 2; mf++) {
        const int row = m0 + wm * 32 + mf * 16 + g;
#pragma unroll
        for (int nf = 0; nf < 8; nf++) {
            const int col = n0 + wn * 64 + nf * 8 + 2 * t4;
            if (omode == 0) {
                float2 v0, v1;
                v0.x = acc[mf][nf][0]; v0.y = acc[mf][nf][1];
                v1.x = acc[mf][nf][2]; v1.y = acc[mf][nf][3];
                *(float2*)&C[(size_t)row * N + col]       = v0;
                *(float2*)&C[(size_t)(row + 8) * N + col] = v1;
            } else if (omode == 1) {
                uint32_t h0, l0, h1, l1;
                pack_hl16(acc[mf][nf][0] * oscale, acc[mf][nf][1] * oscale, h0, l0);
                pack_hl16(acc[mf][nf][2] * oscale, acc[mf][nf][3] * oscale, h1, l1);
                *(uint32_t*)&Ch[(size_t)row * N + col]       = h0;
                *(uint32_t*)&Cl[(size_t)row * N + col]       = l0;
                *(uint32_t*)&Ch[(size_t)(row + 8) * N + col] = h1;
                *(uint32_t*)&Cl[(size_t)(row + 8) * N + col] = l1;
            } else {
                __half2 v0 = __floats2half2_rn(acc[mf][nf][0], acc[mf][nf][1]);
                __half2 v1 = __floats2half2_rn(acc[mf][nf][2], acc[mf][nf][3]);
                *(uint32_t*)&Cs[(size_t)row * N + col]       = *(uint32_t*)&v0;
                *(uint32_t*)&Cs[(size_t)(row + 8) * N + col] = *(uint32_t*)&v1;
            }
        }
    }
}

// Fused Q/K/V projection (z = 0: Q 2-term A + hi/lo out; 1,2: K/V single)
// Q is pre-scaled by 0.125 * log2(e) for the exp2-domain softmax.
#define QSCALE (0.125f * 1.44269504f)

__global__ __launch_bounds__(256, 2)
void proj_fused(const __half* __restrict__ xh, const __half* __restrict__ xl,
                const __half* __restrict__ y1, const __half* __restrict__ w,
                __half* __restrict__ qh, __half* __restrict__ ql,
                __half* __restrict__ k1, __half* __restrict__ v1)
{
    const int z = blockIdx.z;
    if (z == 0 && blockIdx.y >= (BB * NN) / 128) return;

    const __half* Bs = w + (size_t)z * CDIM * CDIM;
    if (z == 0)
        gemm_body<true>(nullptr, qh, ql, nullptr, xh, xl, Bs, QSCALE, 1,
                        CDIM, CDIM, blockIdx.x, blockIdx.y, 0, CDIM >> 6);
    else
        gemm_body<false>(nullptr, nullptr, nullptr, (z == 1) ? k1 : v1,
                         y1, nullptr, Bs, 1.0f, 2,
                         CDIM, CDIM, blockIdx.x, blockIdx.y, 0, CDIM >> 6);
}

// Output projection, split-K=2, single-term A
__global__ __launch_bounds__(256, 2)
void gemm_out_sk(float* __restrict__ P0, float* __restrict__ P1,
                 const __half* __restrict__ A1, const __half* __restrict__ Bs)
{
    const int z = blockIdx.z;
    const int half = (CDIM >> 6) / 2;
    gemm_body<false>(z ? P1 : P0, nullptr, nullptr, nullptr, A1, nullptr, Bs,
                     1.0f, 0, CDIM, CDIM, blockIdx.x, blockIdx.y,
                     z * half, (z + 1) * half);
}

// merge: out = p0 + p1 + bias
__global__ void merge_out(float* __restrict__ out,
                          const float* __restrict__ p0, const float* __restrict__ p1,
                          const float* __restrict__ bias)
{
    const int i = blockIdx.x * blockDim.x + threadIdx.x;
    if (i >= (BB * NN * CDIM) / 4) return;
    const int col4 = i & (CDIM / 4 - 1);
    float4 a = ((const float4*)p0)[i];
    float4 b = ((const float4*)p1)[i];
    float4 bb = ((const float4*)bias)[col4];
    float4 o;
    o.x = a.x + b.x + bb.x; o.y = a.y + b.y + bb.y;
    o.z = a.z + b.z + bb.z; o.w = a.w + b.w + bb.w;
    ((float4*)out)[i] = o;
}

// ---------------------------------------------------------------------------
// Flash attention: QK 2-term, PV single-term, exp2-domain softmax.
// CTA = 128 queries of one (b,h); 8 warps x 16 rows, warp-local softmax.
// Q (hi/lo) persistent in smem; K, V single fp16, double-buffered.
// ---------------------------------------------------------------------------
#define QSM_B   32768
#define KVTILE  8192
#define ASTAGE_B (2 * KVTILE)
#define ATTN_SMEM (QSM_B + 2 * ASTAGE_B)   // 65536

__global__ __launch_bounds__(256, 2)
void attn_mma(__half* __restrict__ O1,
              const __half* __restrict__ Qh, const __half* __restrict__ Ql,
              const __half* __restrict__ K1, const __half* __restrict__ V1)
{
    const int tid  = threadIdx.x;
    const int wid  = tid >> 5;
    const int lane = tid & 31;
    const int g    = lane >> 2;
    const int t4   = lane & 3;
    const int r15  = lane & 15;
    const int hi8  = lane >> 4;
    const int r7   = r15 & 7;
    const int l8   = lane & 7;
    const int lh   = (lane >> 3) & 1;
    const int qt   = blockIdx.x;
    const int h    = blockIdx.y;
    const int b    = blockIdx.z;
    const uint32_t sb = smem_u32(dsm);

    {
#pragma unroll
        for (int k = 0; k < 8; k++) {
            const int j   = tid + k * 256;
            const int hs  = j >> 10;
            const int rem = j & 1023;
            const int row = rem >> 3;
            const int s   = rem & 7;
            const __half* src = (hs ? Ql : Qh) +
                ((size_t)(b * NN + qt * 128 + row) * CDIM + h * DD + s * 8);
            cp16(sb + hs * 16384 + row * 128 + ((s ^ (row & 7)) << 4), src);
        }
        cp_commit();
    }

    const size_t kbase = (size_t)b * LLEN * CDIM + h * DD;

#define ISSUE_KV(cc, buf) do {                                                \
        _Pragma("unroll")                                                     \
        for (int k = 0; k < 4; k++) {                                         \
            const int j    = tid + k * 256;                                   \
            const int tile = j >> 9;                                          \
            const int rem  = j & 511;                                         \
            const int row  = rem >> 3;                                        \
            const int s    = rem & 7;                                         \
            const __half* src = (tile ? V1 : K1) + kbase +                    \
                (size_t)((cc) * 64 + row) * CDIM + s * 8;                     \
            cp16(sb + QSM_B + (buf) * ASTAGE_B + tile * KVTILE                \
                 + row * 128 + ((s ^ (row & 7)) << 4), src);                  \
        }                                                                     \
    } while (0)

    float m0 = -1e30f, m1 = -1e30f, l0 = 0.0f, l1 = 0.0f;
    float o[8][4];
#pragma unroll
    for (int nf = 0; nf < 8; nf++)
#pragma unroll
        for (int j = 0; j < 4; j++) o[nf][j] = 0.0f;

    ISSUE_KV(0, 0); cp_commit();
    cp_wait<0>(); __syncthreads();

    const uint32_t qrow = (uint32_t)((wid * 16 + r15) * 128);

    const int NC = LLEN / 64;
    for (int c = 0; c < NC; c++) {
        const int buf = c & 1;
        if (c + 1 < NC) { ISSUE_KV(c + 1, buf ^ 1); cp_commit(); }

        const uint32_t stg = sb + QSM_B + buf * ASTAGE_B;

        // ---- S (base-2 logits) = (Qh+Ql) K^T ----
        float s[8][4];
#pragma unroll
        for (int nf = 0; nf < 8; nf++)
#pragma unroll
            for (int j = 0; j < 4; j++) s[nf][j] = 0.0f;

#pragma unroll
        for (int kf = 0; kf < 4; kf++) {
            const uint32_t sx = (uint32_t)((((2 * kf + hi8) ^ r7)) << 4);
            uint32_t qh4[4], ql4[4];
            ldsm_x4(qh4, sb + qrow + sx);
            ldsm_x4(ql4, sb + 16384 + qrow + sx);
#pragma unroll
            for (int nfp = 0; nfp < 4; nfp++) {
                uint32_t k4[4];
                ldsm_x4(k4, stg + (uint32_t)((nfp * 16 + r15) * 128) + sx);
                float* s0 = s[2 * nfp];
                float* s1 = s[2 * nfp + 1];
                mma_f16(s0, qh4[0], qh4[1], qh4[2], qh4[3], k4[0], k4[2]);
                mma_f16(s0, ql4[0], ql4[1], ql4[2], ql4[3], k4[0], k4[2]);
                mma_f16(s1, qh4[0], qh4[1], qh4[2], qh4[3], k4[1], k4[3]);
                mma_f16(s1, ql4[0], ql4[1], ql4[2], ql4[3], k4[1], k4[3]);
            }
        }

        // ---- online softmax, base-2 (rows g and g+8) ----
        float cm0 = -1e30f, cm1 = -1e30f;
#pragma unroll
        for (int nf = 0; nf < 8; nf++) {
            cm0 = fmaxf(cm0, fmaxf(s[nf][0], s[nf][1]));
            cm1 = fmaxf(cm1, fmaxf(s[nf][2], s[nf][3]));
        }
        cm0 = fmaxf(cm0, __shfl_xor_sync(0xFFFFFFFFu, cm0, 1));
        cm0 = fmaxf(cm0, __shfl_xor_sync(0xFFFFFFFFu, cm0, 2));
        cm1 = fmaxf(cm1, __shfl_xor_sync(0xFFFFFFFFu, cm1, 1));
        cm1 = fmaxf(cm1, __shfl_xor_sync(0xFFFFFFFFu, cm1, 2));
        const float mn0 = fmaxf(m0, cm0);
        const float mn1 = fmaxf(m1, cm1);
        const float al0 = exp2f(m0 - mn0);
        const float al1 = exp2f(m1 - mn1);
        float sum0 = 0.0f, sum1 = 0.0f;
#pragma unroll
        for (int nf = 0; nf < 8; nf++) {
            s[nf][0] = exp2f(s[nf][0] - mn0); sum0 += s[nf][0];
            s[nf][1] = exp2f(s[nf][1] - mn0); sum0 += s[nf][1];
            s[nf][2] = exp2f(s[nf][2] - mn1); sum1 += s[nf][2];
            s[nf][3] = exp2f(s[nf][3] - mn1); sum1 += s[nf][3];
        }
        sum0 += __shfl_xor_sync(0xFFFFFFFFu, sum0, 1);
        sum0 += __shfl_xor_sync(0xFFFFFFFFu, sum0, 2);
        sum1 += __shfl_xor_sync(0xFFFFFFFFu, sum1, 1);
        sum1 += __shfl_xor_sync(0xFFFFFFFFu, sum1, 2);
        l0 = l0 * al0 + sum0; m0 = mn0;
        l1 = l1 * al1 + sum1; m1 = mn1;
#pragma unroll
        for (int nf = 0; nf < 8; nf++) {
            o[nf][0] *= al0; o[nf][1] *= al0;
            o[nf][2] *= al1; o[nf][3] *= al1;
        }

        // ---- O += P V (single-term P) ----
#pragma unroll
        for (int kf = 0; kf < 4; kf++) {
            uint32_t ph[4];
            {
                __half2 p0 = __floats2half2_rn(s[2 * kf][0],     s[2 * kf][1]);
                __half2 p1 = __floats2half2_rn(s[2 * kf][2],     s[2 * kf][3]);
                __half2 p2 = __floats2half2_rn(s[2 * kf + 1][0], s[2 * kf + 1][1]);
                __half2 p3 = __floats2half2_rn(s[2 * kf + 1][2], s[2 * kf + 1][3]);
                ph[0] = *(uint32_t*)&p0; ph[1] = *(uint32_t*)&p1;
                ph[2] = *(uint32_t*)&p2; ph[3] = *(uint32_t*)&p3;
            }
#pragma unroll
            for (int nf = 0; nf < 8; nf++) {
                uint32_t v0, v1;
                const int vrow = kf * 16 + lh * 8 + l8;
                ldsm_x2_t(v0, v1, stg + KVTILE + (uint32_t)(vrow * 128)
                          + (uint32_t)(((nf ^ l8)) << 4));
                mma_f16(o[nf], ph[0], ph[1], ph[2], ph[3], v0, v1);
            }
        }

        if (c + 1 < NC) cp_wait<0>();
        __syncthreads();
    }

    // ---- normalize and write single fp16 ----
    const float inv0 = 1.0f / l0;
    const float inv1 = 1.0f / l1;
    const int row0 = qt * 128 + wid * 16 + g;
#pragma unroll
    for (int nf = 0; nf < 8; nf++) {
        const int col = h * DD + nf * 8 + 2 * t4;
        const size_t a0 = (size_t)(b * NN + row0) * CDIM + col;
        const size_t a1 = (size_t)(b * NN + row0 + 8) * CDIM + col;
        __half2 v0 = __floats2half2_rn(o[nf][0] * inv0, o[nf][1] * inv0);
        __half2 v1 = __floats2half2_rn(o[nf][2] * inv1, o[nf][3] * inv1);
        *(uint32_t*)&O1[a0] = *(uint32_t*)&v0;
        *(uint32_t*)&O1[a1] = *(uint32_t*)&v1;
    }
#undef ISSUE_KV
}

// ---------------------------------------------------------------------------
// Launch
// ---------------------------------------------------------------------------
extern "C" void kernel_launch(void* const* d_in, const int* in_sizes, int n_in,
                              void* d_out, int out_size)
{
    const float* x  = (const float*)d_in[0];
    const float* y  = (const float*)d_in[1];
    const float* Wq = (const float*)d_in[2];
    const float* Wk = (const float*)d_in[3];
    const float* Wv = (const float*)d_in[4];
    const float* Wp = (const float*)d_in[5];
    const float* bp = (const float*)d_in[6];
    float* out = (float*)d_out;

    __half *xh, *xl, *y1, *w, *qh, *ql, *k1, *v1, *ao;
    float* po;
    cudaGetSymbolAddress((void**)&xh, g_xh);   cudaGetSymbolAddress((void**)&xl, g_xl);
    cudaGetSymbolAddress((void**)&y1, g_y1);
    cudaGetSymbolAddress((void**)&w,  g_w);
    cudaGetSymbolAddress((void**)&qh, g_qh);   cudaGetSymbolAddress((void**)&ql, g_ql);
    cudaGetSymbolAddress((void**)&k1, g_k1);   cudaGetSymbolAddress((void**)&v1, g_v1);
    cudaGetSymbolAddress((void**)&ao, g_ao);
    cudaGetSymbolAddress((void**)&po, g_po);

    cudaFuncSetAttribute(proj_fused,  cudaFuncAttributeMaxDynamicSharedMemorySize, GEMM_SMEM);
    cudaFuncSetAttribute(gemm_out_sk, cudaFuncAttributeMaxDynamicSharedMemorySize, 2 * 2 * GTILE);
    cudaFuncSetAttribute(attn_mma,    cudaFuncAttributeMaxDynamicSharedMemorySize, ATTN_SMEM);

    float* p0 = po;
    float* p1 = po + BB * NN * CDIM;

    // 1. Fused convert
    convert_all<<<(TOT4 + 255) / 256, 256>>>(x, y, Wq, Wk, Wv, Wp, xh, xl, y1, w);

    // 2. Fused Q/K/V projections
    proj_fused<<<dim3(CDIM / 128, (BB * LLEN) / 128, 3), 256, GEMM_SMEM>>>(
        xh, xl, y1, w, qh, ql, k1, v1);

    // 3. Flash attention -> single fp16
    attn_mma<<<dim3(NN / 128, HH, BB), 256, ATTN_SMEM>>>(ao, qh, ql, k1, v1);

    // 4. Output projection, split-K=2 (single-term A)
    gemm_out_sk<<<dim3(CDIM / 128, (BB * NN) / 128, 2), 256, 2 * 2 * GTILE>>>(
        p0, p1, ao, w + 3 * (size_t)CDIM * CDIM);

    // 5. Merge partials + bias
    merge_out<<<((BB * NN * CDIM / 4) + 255) / 256, 256>>>(out, p0, p1, bp);
}

// round 15
// speedup vs baseline: 1.5662x; 1.5662x over previous
#include <cuda_runtime.h>
#include <cuda_fp16.h>
#include <math.h>
#include <stdint.h>

// Problem shape (fixed by the dataset)
#define BB   2
#define NN   1024
#define LLEN 4096
#define CDIM 1024
#define HH   16
#define DD   64

// ---------------- scratch (device globals; no allocs allowed) ---------------
__device__ __half g_xh[BB * NN * CDIM],   g_xl[BB * NN * CDIM];
__device__ __half g_y1[BB * LLEN * CDIM];                  // single fp16
__device__ __half g_w[4 * CDIM * CDIM];                    // single fp16 weights
__device__ __half g_qh[BB * NN * CDIM],   g_ql[BB * NN * CDIM];   // pre-scaled 0.125*log2e
__device__ __half g_k1[BB * LLEN * CDIM];                  // single fp16
__device__ __half g_v1[BB * LLEN * CDIM];                  // single fp16
__device__ __half g_ao[BB * NN * CDIM];                    // single fp16
__device__ float  g_po[2][BB * NN * CDIM];                 // split-K partials

extern __shared__ char dsm[];

// ---------------------------------------------------------------------------
// helpers
// ---------------------------------------------------------------------------
static __device__ __forceinline__ uint32_t smem_u32(const void* p) {
    uint32_t a;
    asm("{ .reg .u64 t; cvta.to.shared.u64 t, %1; cvt.u32.u64 %0, t; }"
        : "=r"(a) : "l"(p));
    return a;
}
static __device__ __forceinline__ void cp16(uint32_t dst, const void* src) {
    asm volatile("cp.async.cg.shared.global [%0], [%1], 16;"
                 :: "r"(dst), "l"(src));
}
static __device__ __forceinline__ void cp_commit() {
    asm volatile("cp.async.commit_group;" ::: "memory");
}
template <int N_>
static __device__ __forceinline__ void cp_wait() {
    asm volatile("cp.async.wait_group %0;" :: "n"(N_) : "memory");
}
// fast 2^x via MUFU (what __expf lowers to, minus the log2e multiply)
static __device__ __forceinline__ float ex2(float x) {
    float y;
    asm("ex2.approx.ftz.f32 %0, %1;" : "=f"(y) : "f"(x));
    return y;
}
static __device__ __forceinline__ void mma_f16(
    float* c, uint32_t a0, uint32_t a1, uint32_t a2, uint32_t a3,
    uint32_t b0, uint32_t b1)
{
    asm volatile(
        "mma.sync.aligned.m16n8k16.row.col.f32.f16.f16.f32 "
        "{%0,%1,%2,%3}, {%4,%5,%6,%7}, {%8,%9}, {%0,%1,%2,%3};"
        : "+f"(c[0]), "+f"(c[1]), "+f"(c[2]), "+f"(c[3])
        : "r"(a0), "r"(a1), "r"(a2), "r"(a3), "r"(b0), "r"(b1));
}
static __device__ __forceinline__ void ldsm_x4(uint32_t* r, uint32_t addr) {
    asm volatile("ldmatrix.sync.aligned.m8n8.x4.shared.b16 {%0,%1,%2,%3}, [%4];"
                 : "=r"(r[0]), "=r"(r[1]), "=r"(r[2]), "=r"(r[3]) : "r"(addr));
}
static __device__ __forceinline__ void ldsm_x2_t(uint32_t& r0, uint32_t& r1, uint32_t addr) {
    asm volatile("ldmatrix.sync.aligned.m8n8.x2.trans.shared.b16 {%0,%1}, [%2];"
                 : "=r"(r0), "=r"(r1) : "r"(addr));
}
static __device__ __forceinline__ void pack_hl16(
    float a, float b, uint32_t& hi, uint32_t& lo)
{
    __half2 h = __floats2half2_rn(a, b);
    __half2 l = __floats2half2_rn(a - __half2float(__low2half(h)),
                                  b - __half2float(__high2half(h)));
    hi = *(uint32_t*)&h;
    lo = *(uint32_t*)&l;
}

// ---------------------------------------------------------------------------
// fused convert: x -> fp16 hi/lo;  y, Wq..Wp -> single fp16.  ONE launch.
// ---------------------------------------------------------------------------
#define X4 ((BB * NN * CDIM) / 4)
#define Y4 ((BB * LLEN * CDIM) / 4)
#define W4 ((CDIM * CDIM) / 4)
#define TOT4 (X4 + Y4 + 4 * W4)

__global__ void convert_all(const float* __restrict__ x, const float* __restrict__ y,
                            const float* __restrict__ Wq, const float* __restrict__ Wk,
                            const float* __restrict__ Wv, const float* __restrict__ Wp,
                            __half* __restrict__ xh, __half* __restrict__ xl,
                            __half* __restrict__ y1, __half* __restrict__ w)
{
    const int i = blockIdx.x * blockDim.x + threadIdx.x;
    if (i >= TOT4) return;

    if (i < X4) {        // hi/lo split for x
        float4 v = ((const float4*)x)[i];
        uint32_t h0, l0, h1, l1;
        pack_hl16(v.x, v.y, h0, l0);
        pack_hl16(v.z, v.w, h1, l1);
        ((uint32_t*)xh)[i * 2 + 0] = h0;
        ((uint32_t*)xh)[i * 2 + 1] = h1;
        ((uint32_t*)xl)[i * 2 + 0] = l0;
        ((uint32_t*)xl)[i * 2 + 1] = l1;
    } else {             // single fp16 for y and weights
        const float* src; __half* dst; int j;
        int r = i - X4;
        if (r < Y4) { src = y; dst = y1; j = r; }
        else {
            r -= Y4;
            const int wsel = r / W4;
            j = r - wsel * W4;
            src = (wsel == 0) ? Wq : (wsel == 1) ? Wk : (wsel == 2) ? Wv : Wp;
            dst = w + (size_t)wsel * CDIM * CDIM;
        }
        float4 v = ((const float4*)src)[j];
        __half2 a = __floats2half2_rn(v.x, v.y);
        __half2 b = __floats2half2_rn(v.z, v.w);
        ((uint32_t*)dst)[j * 2 + 0] = *(uint32_t*)&a;
        ((uint32_t*)dst)[j * 2 + 1] = *(uint32_t*)&b;
    }
}

// ---------------------------------------------------------------------------
// GEMM body, fp16.  TWOA: C = (Ah+Al)*B^T, else C = Ah*B^T.
// BK=64, tile 128x128, 256 thr.  Smem row 128B, swizzle s^(r&7).
// omode: 0 = fp32 C, 1 = fp16 hi/lo (*oscale), 2 = fp16 single.
// ---------------------------------------------------------------------------
#define GTILE  16384
#define GEMM_SMEM (2 * 3 * GTILE)      // worst case (TWOA): 98304

#define LOAD_STAGE(cc, buf) do {                                              \
        const uint32_t bo = (uint32_t)(buf) * STB;                            \
        _Pragma("unroll")                                                     \
        for (int k = 0; k < 4; k++) {                                         \
            const int j   = tid + k * 256;                                    \
            const int row = j >> 3;                                           \
            const int s   = j & 7;                                            \
            const uint32_t doff = (uint32_t)(row * 128 + (((s) ^ (row & 7)) << 4)); \
            cp16(sb + bo + doff, Ah + (size_t)(m0 + row) * K + (cc) * 64 + s * 8); \
            if (TWOA)                                                         \
                cp16(sb + bo + GTILE + doff, Al + (size_t)(m0 + row) * K + (cc) * 64 + s * 8); \
            cp16(sb + bo + BOF + doff, Bs + (size_t)(n0 + row) * K + (cc) * 64 + s * 8); \
        }                                                                     \
    } while (0)

template <bool TWOA>
static __device__ __forceinline__ void gemm_body(
    float* __restrict__ C,
    __half* __restrict__ Ch, __half* __restrict__ Cl, __half* __restrict__ Cs,
    const __half* __restrict__ Ah, const __half* __restrict__ Al,
    const __half* __restrict__ Bs,
    float oscale, int omode, int N, int K, int bx, int by, int c0, int c1)
{
    constexpr uint32_t STB = TWOA ? 3 * GTILE : 2 * GTILE;
    constexpr uint32_t BOF = TWOA ? 2 * GTILE : GTILE;

    const int tid  = threadIdx.x;
    const int wid  = tid >> 5;
    const int lane = tid & 31;
    const int wm   = wid & 3;
    const int wn   = wid >> 2;
    const int g    = lane >> 2;
    const int t4   = lane & 3;
    const int m0   = by * 128;
    const int n0   = bx * 128;
    const int r15  = lane & 15;
    const int hi8  = lane >> 4;
    const int r7   = r15 & 7;

    const uint32_t sb = smem_u32(dsm);

    float acc[2][8][4];
#pragma unroll
    for (int mf = 0; mf < 2; mf++)
#pragma unroll
        for (int nf = 0; nf < 8; nf++)
#pragma unroll
            for (int j = 0; j < 4; j++) acc[mf][nf][j] = 0.0f;

    LOAD_STAGE(c0, 0);
    cp_commit();

    for (int c = c0; c < c1; c++) {
        const int buf = (c - c0) & 1;
        if (c + 1 < c1) {
            LOAD_STAGE(c + 1, buf ^ 1);
            cp_commit();
            cp_wait<1>();
        } else {
            cp_wait<0>();
        }
        __syncthreads();

        const uint32_t stg = sb + (uint32_t)buf * STB;

#pragma unroll
        for (int ks = 0; ks < 4; ks++) {
            const uint32_t sx = (uint32_t)((((2 * ks + hi8) ^ r7)) << 4);
            uint32_t ah[2][4], al[2][4];
#pragma unroll
            for (int mf = 0; mf < 2; mf++) {
                const uint32_t ra = (uint32_t)((wm * 32 + mf * 16 + r15) * 128) + sx;
                ldsm_x4(ah[mf], stg + ra);
                if (TWOA) ldsm_x4(al[mf], stg + GTILE + ra);
            }
#pragma unroll
            for (int nfp = 0; nfp < 4; nfp++) {
                uint32_t b4[4];
                ldsm_x4(b4, stg + BOF +
                        (uint32_t)((wn * 64 + nfp * 16 + r15) * 128) + sx);
#pragma unroll
                for (int mf = 0; mf < 2; mf++) {
                    float* cc0 = acc[mf][2 * nfp];
                    float* cc1 = acc[mf][2 * nfp + 1];
                    mma_f16(cc0, ah[mf][0], ah[mf][1], ah[mf][2], ah[mf][3], b4[0], b4[2]);
                    mma_f16(cc1, ah[mf][0], ah[mf][1], ah[mf][2], ah[mf][3], b4[1], b4[3]);
                    if (TWOA) {
                        mma_f16(cc0, al[mf][0], al[mf][1], al[mf][2], al[mf][3], b4[0], b4[2]);
                        mma_f16(cc1, al[mf][0], al[mf][1], al[mf][2], al[mf][3], b4[1], b4[3]);
                    }
                }
            }
        }
        __syncthreads();
    }

#pragma unroll
    for (int mf = 0; mf < 2; mf++) {
        const int row = m0 + wm * 32 + mf * 16 + g;
#pragma unroll
        for (int nf = 0; nf < 8; nf++) {
            const int col = n0 + wn * 64 + nf * 8 + 2 * t4;
            if (omode == 0) {
                float2 v0, v1;
                v0.x = acc[mf][nf][0]; v0.y = acc[mf][nf][1];
                v1.x = acc[mf][nf][2]; v1.y = acc[mf][nf][3];
                *(float2*)&C[(size_t)row * N + col]       = v0;
                *(float2*)&C[(size_t)(row + 8) * N + col] = v1;
            } else if (omode == 1) {
                uint32_t h0, l0, h1, l1;
                pack_hl16(acc[mf][nf][0] * oscale, acc[mf][nf][1] * oscale, h0, l0);
                pack_hl16(acc[mf][nf][2] * oscale, acc[mf][nf][3] * oscale, h1, l1);
                *(uint32_t*)&Ch[(size_t)row * N + col]       = h0;
                *(uint32_t*)&Cl[(size_t)row * N + col]       = l0;
                *(uint32_t*)&Ch[(size_t)(row + 8) * N + col] = h1;
                *(uint32_t*)&Cl[(size_t)(row + 8) * N + col] = l1;
            } else {
                __half2 v0 = __floats2half2_rn(acc[mf][nf][0], acc[mf][nf][1]);
                __half2 v1 = __floats2half2_rn(acc[mf][nf][2], acc[mf][nf][3]);
                *(uint32_t*)&Cs[(size_t)row * N + col]       = *(uint32_t*)&v0;
                *(uint32_t*)&Cs[(size_t)(row + 8) * N + col] = *(uint32_t*)&v1;
            }
        }
    }
}

// Fused Q/K/V projection (z = 0: Q 2-term A + hi/lo out; 1,2: K/V single)
// Q is pre-scaled by 0.125 * log2(e) for the base-2 softmax.
#define QSCALE (0.125f * 1.44269504f)

__global__ __launch_bounds__(256, 2)
void proj_fused(const __half* __restrict__ xh, const __half* __restrict__ xl,
                const __half* __restrict__ y1, const __half* __restrict__ w,
                __half* __restrict__ qh, __half* __restrict__ ql,
                __half* __restrict__ k1, __half* __restrict__ v1)
{
    const int z = blockIdx.z;
    if (z == 0 && blockIdx.y >= (BB * NN) / 128) return;

    const __half* Bs = w + (size_t)z * CDIM * CDIM;
    if (z == 0)
        gemm_body<true>(nullptr, qh, ql, nullptr, xh, xl, Bs, QSCALE, 1,
                        CDIM, CDIM, blockIdx.x, blockIdx.y, 0, CDIM >> 6);
    else
        gemm_body<false>(nullptr, nullptr, nullptr, (z == 1) ? k1 : v1,
                         y1, nullptr, Bs, 1.0f, 2,
                         CDIM, CDIM, blockIdx.x, blockIdx.y, 0, CDIM >> 6);
}

// Output projection, split-K=2, single-term A
__global__ __launch_bounds__(256, 2)
void gemm_out_sk(float* __restrict__ P0, float* __restrict__ P1,
                 const __half* __restrict__ A1, const __half* __restrict__ Bs)
{
    const int z = blockIdx.z;
    const int half = (CDIM >> 6) / 2;
    gemm_body<false>(z ? P1 : P0, nullptr, nullptr, nullptr, A1, nullptr, Bs,
                     1.0f, 0, CDIM, CDIM, blockIdx.x, blockIdx.y,
                     z * half, (z + 1) * half);
}

// merge: out = p0 + p1 + bias
__global__ void merge_out(float* __restrict__ out,
                          const float* __restrict__ p0, const float* __restrict__ p1,
                          const float* __restrict__ bias)
{
    const int i = blockIdx.x * blockDim.x + threadIdx.x;
    if (i >= (BB * NN * CDIM) / 4) return;
    const int col4 = i & (CDIM / 4 - 1);
    float4 a = ((const float4*)p0)[i];
    float4 b = ((const float4*)p1)[i];
    float4 bb = ((const float4*)bias)[col4];
    float4 o;
    o.x = a.x + b.x + bb.x; o.y = a.y + b.y + bb.y;
    o.z = a.z + b.z + bb.z; o.w = a.w + b.w + bb.w;
    ((float4*)out)[i] = o;
}

// ---------------------------------------------------------------------------
// Flash attention: QK 2-term, PV single-term, base-2 softmax via ex2.approx.
// CTA = 128 queries of one (b,h); 8 warps x 16 rows, warp-local softmax.
// Q (hi/lo) persistent in smem; K, V single fp16, double-buffered.
// ---------------------------------------------------------------------------
#define QSM_B   32768
#define KVTILE  8192
#define ASTAGE_B (2 * KVTILE)
#define ATTN_SMEM (QSM_B + 2 * ASTAGE_B)   // 65536

__global__ __launch_bounds__(256, 2)
void attn_mma(__half* __restrict__ O1,
              const __half* __restrict__ Qh, const __half* __restrict__ Ql,
              const __half* __restrict__ K1, const __half* __restrict__ V1)
{
    const int tid  = threadIdx.x;
    const int wid  = tid >> 5;
    const int lane = tid & 31;
    const int g    = lane >> 2;
    const int t4   = lane & 3;
    const int r15  = lane & 15;
    const int hi8  = lane >> 4;
    const int r7   = r15 & 7;
    const int l8   = lane & 7;
    const int lh   = (lane >> 3) & 1;
    const int qt   = blockIdx.x;
    const int h    = blockIdx.y;
    const int b    = blockIdx.z;
    const uint32_t sb = smem_u32(dsm);

    {
#pragma unroll
        for (int k = 0; k < 8; k++) {
            const int j   = tid + k * 256;
            const int hs  = j >> 10;
            const int rem = j & 1023;
            const int row = rem >> 3;
            const int s   = rem & 7;
            const __half* src = (hs ? Ql : Qh) +
                ((size_t)(b * NN + qt * 128 + row) * CDIM + h * DD + s * 8);
            cp16(sb + hs * 16384 + row * 128 + ((s ^ (row & 7)) << 4), src);
        }
        cp_commit();
    }

    const size_t kbase = (size_t)b * LLEN * CDIM + h * DD;

#define ISSUE_KV(cc, buf) do {                                                \
        _Pragma("unroll")                                                     \
        for (int k = 0; k < 4; k++) {                                         \
            const int j    = tid + k * 256;                                   \
            const int tile = j >> 9;                                          \
            const int rem  = j & 511;                                         \
            const int row  = rem >> 3;                                        \
            const int s    = rem & 7;                                         \
            const __half* src = (tile ? V1 : K1) + kbase +                    \
                (size_t)((cc) * 64 + row) * CDIM + s * 8;                     \
            cp16(sb + QSM_B + (buf) * ASTAGE_B + tile * KVTILE                \
                 + row * 128 + ((s ^ (row & 7)) << 4), src);                  \
        }                                                                     \
    } while (0)

    float m0 = -1e30f, m1 = -1e30f, l0 = 0.0f, l1 = 0.0f;
    float o[8][4];
#pragma unroll
    for (int nf = 0; nf < 8; nf++)
#pragma unroll
        for (int j = 0; j < 4; j++) o[nf][j] = 0.0f;

    ISSUE_KV(0, 0); cp_commit();
    cp_wait<0>(); __syncthreads();

    const uint32_t qrow = (uint32_t)((wid * 16 + r15) * 128);

    const int NC = LLEN / 64;
    for (int c = 0; c < NC; c++) {
        const int buf = c & 1;
        if (c + 1 < NC) { ISSUE_KV(c + 1, buf ^ 1); cp_commit(); }

        const uint32_t stg = sb + QSM_B + buf * ASTAGE_B;

        // ---- S (base-2 logits) = (Qh+Ql) K^T ----
        float s[8][4];
#pragma unroll
        for (int nf = 0; nf < 8; nf++)
#pragma unroll
            for (int j = 0; j < 4; j++) s[nf][j] = 0.0f;

#pragma unroll
        for (int kf = 0; kf < 4; kf++) {
            const uint32_t sx = (uint32_t)((((2 * kf + hi8) ^ r7)) << 4);
            uint32_t qh4[4], ql4[4];
            ldsm_x4(qh4, sb + qrow + sx);
            ldsm_x4(ql4, sb + 16384 + qrow + sx);
#pragma unroll
            for (int nfp = 0; nfp < 4; nfp++) {
                uint32_t k4[4];
                ldsm_x4(k4, stg + (uint32_t)((nfp * 16 + r15) * 128) + sx);
                float* s0 = s[2 * nfp];
                float* s1 = s[2 * nfp + 1];
                mma_f16(s0, qh4[0], qh4[1], qh4[2], qh4[3], k4[0], k4[2]);
                mma_f16(s0, ql4[0], ql4[1], ql4[2], ql4[3], k4[0], k4[2]);
                mma_f16(s1, qh4[0], qh4[1], qh4[2], qh4[3], k4[1], k4[3]);
                mma_f16(s1, ql4[0], ql4[1], ql4[2], ql4[3], k4[1], k4[3]);
            }
        }

        // ---- online softmax, base-2 via ex2.approx (rows g and g+8) ----
        float cm0 = -1e30f, cm1 = -1e30f;
#pragma unroll
        for (int nf = 0; nf < 8; nf++) {
            cm0 = fmaxf(cm0, fmaxf(s[nf][0], s[nf][1]));
            cm1 = fmaxf(cm1, fmaxf(s[nf][2], s[nf][3]));
        }
        cm0 = fmaxf(cm0, __shfl_xor_sync(0xFFFFFFFFu, cm0, 1));
        cm0 = fmaxf(cm0, __shfl_xor_sync(0xFFFFFFFFu, cm0, 2));
        cm1 = fmaxf(cm1, __shfl_xor_sync(0xFFFFFFFFu, cm1, 1));
        cm1 = fmaxf(cm1, __shfl_xor_sync(0xFFFFFFFFu, cm1, 2));
        const float mn0 = fmaxf(m0, cm0);
        const float mn1 = fmaxf(m1, cm1);
        const float al0 = ex2(m0 - mn0);
        const float al1 = ex2(m1 - mn1);
        float sum0 = 0.0f, sum1 = 0.0f;
#pragma unroll
        for (int nf = 0; nf < 8; nf++) {
            s[nf][0] = ex2(s[nf][0] - mn0); sum0 += s[nf][0];
            s[nf][1] = ex2(s[nf][1] - mn0); sum0 += s[nf][1];
            s[nf][2] = ex2(s[nf][2] - mn1); sum1 += s[nf][2];
            s[nf][3] = ex2(s[nf][3] - mn1); sum1 += s[nf][3];
        }
        sum0 += __shfl_xor_sync(0xFFFFFFFFu, sum0, 1);
        sum0 += __shfl_xor_sync(0xFFFFFFFFu, sum0, 2);
        sum1 += __shfl_xor_sync(0xFFFFFFFFu, sum1, 1);
        sum1 += __shfl_xor_sync(0xFFFFFFFFu, sum1, 2);
        l0 = l0 * al0 + sum0; m0 = mn0;
        l1 = l1 * al1 + sum1; m1 = mn1;
#pragma unroll
        for (int nf = 0; nf < 8; nf++) {
            o[nf][0] *= al0; o[nf][1] *= al0;
            o[nf][2] *= al1; o[nf][3] *= al1;
        }

        // ---- O += P V (single-term P) ----
#pragma unroll
        for (int kf = 0; kf < 4; kf++) {
            uint32_t ph[4];
            {
                __half2 p0 = __floats2half2_rn(s[2 * kf][0],     s[2 * kf][1]);
                __half2 p1 = __floats2half2_rn(s[2 * kf][2],     s[2 * kf][3]);
                __half2 p2 = __floats2half2_rn(s[2 * kf + 1][0], s[2 * kf + 1][1]);
                __half2 p3 = __floats2half2_rn(s[2 * kf + 1][2], s[2 * kf + 1][3]);
                ph[0] = *(uint32_t*)&p0; ph[1] = *(uint32_t*)&p1;
                ph[2] = *(uint32_t*)&p2; ph[3] = *(uint32_t*)&p3;
            }
#pragma unroll
            for (int nf = 0; nf < 8; nf++) {
                uint32_t v0, v1;
                const int vrow = kf * 16 + lh * 8 + l8;
                ldsm_x2_t(v0, v1, stg + KVTILE + (uint32_t)(vrow * 128)
                          + (uint32_t)(((nf ^ l8)) << 4));
                mma_f16(o[nf], ph[0], ph[1], ph[2], ph[3], v0, v1);
            }
        }

        if (c + 1 < NC) cp_wait<0>();
        __syncthreads();
    }

    // ---- normalize and write single fp16 ----
    const float inv0 = 1.0f / l0;
    const float inv1 = 1.0f / l1;
    const int row0 = qt * 128 + wid * 16 + g;
#pragma unroll
    for (int nf = 0; nf < 8; nf++) {
        const int col = h * DD + nf * 8 + 2 * t4;
        const size_t a0 = (size_t)(b * NN + row0) * CDIM + col;
        const size_t a1 = (size_t)(b * NN + row0 + 8) * CDIM + col;
        __half2 v0 = __floats2half2_rn(o[nf][0] * inv0, o[nf][1] * inv0);
        __half2 v1 = __floats2half2_rn(o[nf][2] * inv1, o[nf][3] * inv1);
        *(uint32_t*)&O1[a0] = *(uint32_t*)&v0;
        *(uint32_t*)&O1[a1] = *(uint32_t*)&v1;
    }
#undef ISSUE_KV
}

// ---------------------------------------------------------------------------
// Launch
// ---------------------------------------------------------------------------
extern "C" void kernel_launch(void* const* d_in, const int* in_sizes, int n_in,
                              void* d_out, int out_size)
{
    const float* x  = (const float*)d_in[0];
    const float* y  = (const float*)d_in[1];
    const float* Wq = (const float*)d_in[2];
    const float* Wk = (const float*)d_in[3];
    const float* Wv = (const float*)d_in[4];
    const float* Wp = (const float*)d_in[5];
    const float* bp = (const float*)d_in[6];
    float* out = (float*)d_out;

    __half *xh, *xl, *y1, *w, *qh, *ql, *k1, *v1, *ao;
    float* po;
    cudaGetSymbolAddress((void**)&xh, g_xh);   cudaGetSymbolAddress((void**)&xl, g_xl);
    cudaGetSymbolAddress((void**)&y1, g_y1);
    cudaGetSymbolAddress((void**)&w,  g_w);
    cudaGetSymbolAddress((void**)&qh, g_qh);   cudaGetSymbolAddress((void**)&ql, g_ql);
    cudaGetSymbolAddress((void**)&k1, g_k1);   cudaGetSymbolAddress((void**)&v1, g_v1);
    cudaGetSymbolAddress((void**)&ao, g_ao);
    cudaGetSymbolAddress((void**)&po, g_po);

    cudaFuncSetAttribute(proj_fused,  cudaFuncAttributeMaxDynamicSharedMemorySize, GEMM_SMEM);
    cudaFuncSetAttribute(gemm_out_sk, cudaFuncAttributeMaxDynamicSharedMemorySize, 2 * 2 * GTILE);
    cudaFuncSetAttribute(attn_mma,    cudaFuncAttributeMaxDynamicSharedMemorySize, ATTN_SMEM);

    float* p0 = po;
    float* p1 = po + BB * NN * CDIM;

    // 1. Fused convert
    convert_all<<<(TOT4 + 255) / 256, 256>>>(x, y, Wq, Wk, Wv, Wp, xh, xl, y1, w);

    // 2. Fused Q/K/V projections
    proj_fused<<<dim3(CDIM / 128, (BB * LLEN) / 128, 3), 256, GEMM_SMEM>>>(
        xh, xl, y1, w, qh, ql, k1, v1);

    // 3. Flash attention -> single fp16
    attn_mma<<<dim3(NN / 128, HH, BB), 256, ATTN_SMEM>>>(ao, qh, ql, k1, v1);

    // 4. Output projection, split-K=2 (single-term A)
    gemm_out_sk<<<dim3(CDIM / 128, (BB * NN) / 128, 2), 256, 2 * 2 * GTILE>>>(
        p0, p1, ao, w + 3 * (size_t)CDIM * CDIM);

    // 5. Merge partials + bias
    merge_out<<<((BB * NN * CDIM / 4) + 255) / 256, 256>>>(out, p0, p1, bp);
}

// round 16
// speedup vs baseline: 1.7804x; 1.1368x over previous
#include <cuda_runtime.h>
#include <cuda_fp16.h>
#include <math.h>
#include <stdint.h>

// Problem shape (fixed by the dataset)
#define BB   2
#define NN   1024
#define LLEN 4096
#define CDIM 1024
#define HH   16
#define DD   64

// ---------------- scratch (device globals; no allocs allowed) ---------------
__device__ __half g_xh[BB * NN * CDIM],   g_xl[BB * NN * CDIM];
__device__ __half g_y1[BB * LLEN * CDIM];                  // single fp16
__device__ __half g_w[4 * CDIM * CDIM];                    // single fp16 weights
__device__ __half g_q1[BB * NN * CDIM];                    // single fp16, pre-scaled
__device__ __half g_k1[BB * LLEN * CDIM];                  // single fp16
__device__ __half g_v1[BB * LLEN * CDIM];                  // single fp16
__device__ __half g_ao[BB * NN * CDIM];                    // single fp16
__device__ float  g_po[2][BB * NN * CDIM];                 // split-K partials

extern __shared__ char dsm[];

// ---------------------------------------------------------------------------
// helpers
// ---------------------------------------------------------------------------
static __device__ __forceinline__ uint32_t smem_u32(const void* p) {
    uint32_t a;
    asm("{ .reg .u64 t; cvta.to.shared.u64 t, %1; cvt.u32.u64 %0, t; }"
        : "=r"(a) : "l"(p));
    return a;
}
static __device__ __forceinline__ void cp16(uint32_t dst, const void* src) {
    asm volatile("cp.async.cg.shared.global [%0], [%1], 16;"
                 :: "r"(dst), "l"(src));
}
static __device__ __forceinline__ void cp_commit() {
    asm volatile("cp.async.commit_group;" ::: "memory");
}
template <int N_>
static __device__ __forceinline__ void cp_wait() {
    asm volatile("cp.async.wait_group %0;" :: "n"(N_) : "memory");
}
// fast 2^x via MUFU
static __device__ __forceinline__ float ex2(float x) {
    float y;
    asm("ex2.approx.ftz.f32 %0, %1;" : "=f"(y) : "f"(x));
    return y;
}
static __device__ __forceinline__ void mma_f16(
    float* c, uint32_t a0, uint32_t a1, uint32_t a2, uint32_t a3,
    uint32_t b0, uint32_t b1)
{
    asm volatile(
        "mma.sync.aligned.m16n8k16.row.col.f32.f16.f16.f32 "
        "{%0,%1,%2,%3}, {%4,%5,%6,%7}, {%8,%9}, {%0,%1,%2,%3};"
        : "+f"(c[0]), "+f"(c[1]), "+f"(c[2]), "+f"(c[3])
        : "r"(a0), "r"(a1), "r"(a2), "r"(a3), "r"(b0), "r"(b1));
}
static __device__ __forceinline__ void ldsm_x4(uint32_t* r, uint32_t addr) {
    asm volatile("ldmatrix.sync.aligned.m8n8.x4.shared.b16 {%0,%1,%2,%3}, [%4];"
                 : "=r"(r[0]), "=r"(r[1]), "=r"(r[2]), "=r"(r[3]) : "r"(addr));
}
static __device__ __forceinline__ void ldsm_x2_t(uint32_t& r0, uint32_t& r1, uint32_t addr) {
    asm volatile("ldmatrix.sync.aligned.m8n8.x2.trans.shared.b16 {%0,%1}, [%2];"
                 : "=r"(r0), "=r"(r1) : "r"(addr));
}
static __device__ __forceinline__ void pack_hl16(
    float a, float b, uint32_t& hi, uint32_t& lo)
{
    __half2 h = __floats2half2_rn(a, b);
    __half2 l = __floats2half2_rn(a - __half2float(__low2half(h)),
                                  b - __half2float(__high2half(h)));
    hi = *(uint32_t*)&h;
    lo = *(uint32_t*)&l;
}

// ---------------------------------------------------------------------------
// fused convert: x -> fp16 hi/lo;  y, Wq..Wp -> single fp16.  ONE launch.
// ---------------------------------------------------------------------------
#define X4 ((BB * NN * CDIM) / 4)
#define Y4 ((BB * LLEN * CDIM) / 4)
#define W4 ((CDIM * CDIM) / 4)
#define TOT4 (X4 + Y4 + 4 * W4)

__global__ void convert_all(const float* __restrict__ x, const float* __restrict__ y,
                            const float* __restrict__ Wq, const float* __restrict__ Wk,
                            const float* __restrict__ Wv, const float* __restrict__ Wp,
                            __half* __restrict__ xh, __half* __restrict__ xl,
                            __half* __restrict__ y1, __half* __restrict__ w)
{
    const int i = blockIdx.x * blockDim.x + threadIdx.x;
    if (i >= TOT4) return;

    if (i < X4) {        // hi/lo split for x
        float4 v = ((const float4*)x)[i];
        uint32_t h0, l0, h1, l1;
        pack_hl16(v.x, v.y, h0, l0);
        pack_hl16(v.z, v.w, h1, l1);
        ((uint32_t*)xh)[i * 2 + 0] = h0;
        ((uint32_t*)xh)[i * 2 + 1] = h1;
        ((uint32_t*)xl)[i * 2 + 0] = l0;
        ((uint32_t*)xl)[i * 2 + 1] = l1;
    } else {             // single fp16 for y and weights
        const float* src; __half* dst; int j;
        int r = i - X4;
        if (r < Y4) { src = y; dst = y1; j = r; }
        else {
            r -= Y4;
            const int wsel = r / W4;
            j = r - wsel * W4;
            src = (wsel == 0) ? Wq : (wsel == 1) ? Wk : (wsel == 2) ? Wv : Wp;
            dst = w + (size_t)wsel * CDIM * CDIM;
        }
        float4 v = ((const float4*)src)[j];
        __half2 a = __floats2half2_rn(v.x, v.y);
        __half2 b = __floats2half2_rn(v.z, v.w);
        ((uint32_t*)dst)[j * 2 + 0] = *(uint32_t*)&a;
        ((uint32_t*)dst)[j * 2 + 1] = *(uint32_t*)&b;
    }
}

// ---------------------------------------------------------------------------
// GEMM body, fp16.  TWOA: C = (Ah+Al)*B^T, else C = Ah*B^T.
// BK=64, tile 128x128, 256 thr.  Smem row 128B, swizzle s^(r&7).
// omode: 0 = fp32 C, 2 = fp16 single (*oscale).
// ---------------------------------------------------------------------------
#define GTILE  16384
#define GEMM_SMEM (2 * 3 * GTILE)      // worst case (TWOA): 98304

#define LOAD_STAGE(cc, buf) do {                                              \
        const uint32_t bo = (uint32_t)(buf) * STB;                            \
        _Pragma("unroll")                                                     \
        for (int k = 0; k < 4; k++) {                                         \
            const int j   = tid + k * 256;                                    \
            const int row = j >> 3;                                           \
            const int s   = j & 7;                                            \
            const uint32_t doff = (uint32_t)(row * 128 + (((s) ^ (row & 7)) << 4)); \
            cp16(sb + bo + doff, Ah + (size_t)(m0 + row) * K + (cc) * 64 + s * 8); \
            if (TWOA)                                                         \
                cp16(sb + bo + GTILE + doff, Al + (size_t)(m0 + row) * K + (cc) * 64 + s * 8); \
            cp16(sb + bo + BOF + doff, Bs + (size_t)(n0 + row) * K + (cc) * 64 + s * 8); \
        }                                                                     \
    } while (0)

template <bool TWOA>
static __device__ __forceinline__ void gemm_body(
    float* __restrict__ C, __half* __restrict__ Cs,
    const __half* __restrict__ Ah, const __half* __restrict__ Al,
    const __half* __restrict__ Bs,
    float oscale, int omode, int N, int K, int bx, int by, int c0, int c1)
{
    constexpr uint32_t STB = TWOA ? 3 * GTILE : 2 * GTILE;
    constexpr uint32_t BOF = TWOA ? 2 * GTILE : GTILE;

    const int tid  = threadIdx.x;
    const int wid  = tid >> 5;
    const int lane = tid & 31;
    const int wm   = wid & 3;
    const int wn   = wid >> 2;
    const int g    = lane >> 2;
    const int t4   = lane & 3;
    const int m0   = by * 128;
    const int n0   = bx * 128;
    const int r15  = lane & 15;
    const int hi8  = lane >> 4;
    const int r7   = r15 & 7;

    const uint32_t sb = smem_u32(dsm);

    float acc[2][8][4];
#pragma unroll
    for (int mf = 0; mf < 2; mf++)
#pragma unroll
        for (int nf = 0; nf < 8; nf++)
#pragma unroll
            for (int j = 0; j < 4; j++) acc[mf][nf][j] = 0.0f;

    LOAD_STAGE(c0, 0);
    cp_commit();

    for (int c = c0; c < c1; c++) {
        const int buf = (c - c0) & 1;
        if (c + 1 < c1) {
            LOAD_STAGE(c + 1, buf ^ 1);
            cp_commit();
            cp_wait<1>();
        } else {
            cp_wait<0>();
        }
        __syncthreads();

        const uint32_t stg = sb + (uint32_t)buf * STB;

#pragma unroll
        for (int ks = 0; ks < 4; ks++) {
            const uint32_t sx = (uint32_t)((((2 * ks + hi8) ^ r7)) << 4);
            uint32_t ah[2][4], al[2][4];
#pragma unroll
            for (int mf = 0; mf < 2; mf++) {
                const uint32_t ra = (uint32_t)((wm * 32 + mf * 16 + r15) * 128) + sx;
                ldsm_x4(ah[mf], stg + ra);
                if (TWOA) ldsm_x4(al[mf], stg + GTILE + ra);
            }
#pragma unroll
            for (int nfp = 0; nfp < 4; nfp++) {
                uint32_t b4[4];
                ldsm_x4(b4, stg + BOF +
                        (uint32_t)((wn * 64 + nfp * 16 + r15) * 128) + sx);
#pragma unroll
                for (int mf = 0; mf < 2; mf++) {
                    float* cc0 = acc[mf][2 * nfp];
                    float* cc1 = acc[mf][2 * nfp + 1];
                    mma_f16(cc0, ah[mf][0], ah[mf][1], ah[mf][2], ah[mf][3], b4[0], b4[2]);
                    mma_f16(cc1, ah[mf][0], ah[mf][1], ah[mf][2], ah[mf][3], b4[1], b4[3]);
                    if (TWOA) {
                        mma_f16(cc0, al[mf][0], al[mf][1], al[mf][2], al[mf][3], b4[0], b4[2]);
                        mma_f16(cc1, al[mf][0], al[mf][1], al[mf][2], al[mf][3], b4[1], b4[3]);
                    }
                }
            }
        }
        __syncthreads();
    }

#pragma unroll
    for (int mf = 0; mf < 2; mf++) {
        const int row = m0 + wm * 32 + mf * 16 + g;
#pragma unroll
        for (int nf = 0; nf < 8; nf++) {
            const int col = n0 + wn * 64 + nf * 8 + 2 * t4;
            if (omode == 0) {
                float2 v0, v1;
                v0.x = acc[mf][nf][0]; v0.y = acc[mf][nf][1];
                v1.x = acc[mf][nf][2]; v1.y = acc[mf][nf][3];
                *(float2*)&C[(size_t)row * N + col]       = v0;
                *(float2*)&C[(size_t)(row + 8) * N + col] = v1;
            } else {
                __half2 v0 = __floats2half2_rn(acc[mf][nf][0] * oscale,
                                               acc[mf][nf][1] * oscale);
                __half2 v1 = __floats2half2_rn(acc[mf][nf][2] * oscale,
                                               acc[mf][nf][3] * oscale);
                *(uint32_t*)&Cs[(size_t)row * N + col]       = *(uint32_t*)&v0;
                *(uint32_t*)&Cs[(size_t)(row + 8) * N + col] = *(uint32_t*)&v1;
            }
        }
    }
}

// Fused Q/K/V projection (z = 0: Q 2-term A input, single out, pre-scaled;
// 1,2: K/V fully single).  Q pre-scaled by 0.125 * log2(e).
#define QSCALE (0.125f * 1.44269504f)

__global__ __launch_bounds__(256, 2)
void proj_fused(const __half* __restrict__ xh, const __half* __restrict__ xl,
                const __half* __restrict__ y1, const __half* __restrict__ w,
                __half* __restrict__ q1, __half* __restrict__ k1,
                __half* __restrict__ v1)
{
    const int z = blockIdx.z;
    if (z == 0 && blockIdx.y >= (BB * NN) / 128) return;

    const __half* Bs = w + (size_t)z * CDIM * CDIM;
    if (z == 0)
        gemm_body<true>(nullptr, q1, xh, xl, Bs, QSCALE, 2,
                        CDIM, CDIM, blockIdx.x, blockIdx.y, 0, CDIM >> 6);
    else
        gemm_body<false>(nullptr, (z == 1) ? k1 : v1, y1, nullptr, Bs, 1.0f, 2,
                         CDIM, CDIM, blockIdx.x, blockIdx.y, 0, CDIM >> 6);
}

// Output projection, split-K=2, single-term A
__global__ __launch_bounds__(256, 2)
void gemm_out_sk(float* __restrict__ P0, float* __restrict__ P1,
                 const __half* __restrict__ A1, const __half* __restrict__ Bs)
{
    const int z = blockIdx.z;
    const int half = (CDIM >> 6) / 2;
    gemm_body<false>(z ? P1 : P0, nullptr, A1, nullptr, Bs,
                     1.0f, 0, CDIM, CDIM, blockIdx.x, blockIdx.y,
                     z * half, (z + 1) * half);
}

// merge: out = p0 + p1 + bias
__global__ void merge_out(float* __restrict__ out,
                          const float* __restrict__ p0, const float* __restrict__ p1,
                          const float* __restrict__ bias)
{
    const int i = blockIdx.x * blockDim.x + threadIdx.x;
    if (i >= (BB * NN * CDIM) / 4) return;
    const int col4 = i & (CDIM / 4 - 1);
    float4 a = ((const float4*)p0)[i];
    float4 b = ((const float4*)p1)[i];
    float4 bb = ((const float4*)bias)[col4];
    float4 o;
    o.x = a.x + b.x + bb.x; o.y = a.y + b.y + bb.y;
    o.z = a.z + b.z + bb.z; o.w = a.w + b.w + bb.w;
    ((float4*)out)[i] = o;
}

// ---------------------------------------------------------------------------
// Flash attention: all-single fp16, base-2 softmax via ex2.approx.
// CTA = 128 queries of one (b,h); 8 warps x 16 rows, warp-local softmax.
// Q single persistent in smem (16KB); K, V single fp16, double-buffered.
// ---------------------------------------------------------------------------
#define QSM_B   16384
#define KVTILE  8192
#define ASTAGE_B (2 * KVTILE)
#define ATTN_SMEM (QSM_B + 2 * ASTAGE_B)   // 49152

__global__ __launch_bounds__(256, 2)
void attn_mma(__half* __restrict__ O1,
              const __half* __restrict__ Q1,
              const __half* __restrict__ K1, const __half* __restrict__ V1)
{
    const int tid  = threadIdx.x;
    const int wid  = tid >> 5;
    const int lane = tid & 31;
    const int g    = lane >> 2;
    const int t4   = lane & 3;
    const int r15  = lane & 15;
    const int hi8  = lane >> 4;
    const int r7   = r15 & 7;
    const int l8   = lane & 7;
    const int lh   = (lane >> 3) & 1;
    const int qt   = blockIdx.x;
    const int h    = blockIdx.y;
    const int b    = blockIdx.z;
    const uint32_t sb = smem_u32(dsm);

    // ---- stage Q (single) into persistent smem ----
    {
#pragma unroll
        for (int k = 0; k < 4; k++) {
            const int j   = tid + k * 256;
            const int row = j >> 3;
            const int s   = j & 7;
            const __half* src = Q1 +
                ((size_t)(b * NN + qt * 128 + row) * CDIM + h * DD + s * 8);
            cp16(sb + row * 128 + ((s ^ (row & 7)) << 4), src);
        }
        cp_commit();
    }

    const size_t kbase = (size_t)b * LLEN * CDIM + h * DD;

#define ISSUE_KV(cc, buf) do {                                                \
        _Pragma("unroll")                                                     \
        for (int k = 0; k < 4; k++) {                                         \
            const int j    = tid + k * 256;                                   \
            const int tile = j >> 9;                                          \
            const int rem  = j & 511;                                         \
            const int row  = rem >> 3;                                        \
            const int s    = rem & 7;                                         \
            const __half* src = (tile ? V1 : K1) + kbase +                    \
                (size_t)((cc) * 64 + row) * CDIM + s * 8;                     \
            cp16(sb + QSM_B + (buf) * ASTAGE_B + tile * KVTILE                \
                 + row * 128 + ((s ^ (row & 7)) << 4), src);                  \
        }                                                                     \
    } while (0)

    float m0 = -1e30f, m1 = -1e30f, l0 = 0.0f, l1 = 0.0f;
    float o[8][4];
#pragma unroll
    for (int nf = 0; nf < 8; nf++)
#pragma unroll
        for (int j = 0; j < 4; j++) o[nf][j] = 0.0f;

    ISSUE_KV(0, 0); cp_commit();
    cp_wait<0>(); __syncthreads();

    const uint32_t qrow = (uint32_t)((wid * 16 + r15) * 128);

    const int NC = LLEN / 64;
    for (int c = 0; c < NC; c++) {
        const int buf = c & 1;
        if (c + 1 < NC) { ISSUE_KV(c + 1, buf ^ 1); cp_commit(); }

        const uint32_t stg = sb + QSM_B + buf * ASTAGE_B;

        // ---- S (base-2 logits) = Q K^T ----
        float s[8][4];
#pragma unroll
        for (int nf = 0; nf < 8; nf++)
#pragma unroll
            for (int j = 0; j < 4; j++) s[nf][j] = 0.0f;

#pragma unroll
        for (int kf = 0; kf < 4; kf++) {
            const uint32_t sx = (uint32_t)((((2 * kf + hi8) ^ r7)) << 4);
            uint32_t q4[4];
            ldsm_x4(q4, sb + qrow + sx);
#pragma unroll
            for (int nfp = 0; nfp < 4; nfp++) {
                uint32_t k4[4];
                ldsm_x4(k4, stg + (uint32_t)((nfp * 16 + r15) * 128) + sx);
                mma_f16(s[2 * nfp],     q4[0], q4[1], q4[2], q4[3], k4[0], k4[2]);
                mma_f16(s[2 * nfp + 1], q4[0], q4[1], q4[2], q4[3], k4[1], k4[3]);
            }
        }

        // ---- online softmax, base-2 via ex2.approx (rows g and g+8) ----
        float cm0 = -1e30f, cm1 = -1e30f;
#pragma unroll
        for (int nf = 0; nf < 8; nf++) {
            cm0 = fmaxf(cm0, fmaxf(s[nf][0], s[nf][1]));
            cm1 = fmaxf(cm1, fmaxf(s[nf][2], s[nf][3]));
        }
        cm0 = fmaxf(cm0, __shfl_xor_sync(0xFFFFFFFFu, cm0, 1));
        cm0 = fmaxf(cm0, __shfl_xor_sync(0xFFFFFFFFu, cm0, 2));
        cm1 = fmaxf(cm1, __shfl_xor_sync(0xFFFFFFFFu, cm1, 1));
        cm1 = fmaxf(cm1, __shfl_xor_sync(0xFFFFFFFFu, cm1, 2));
        const float mn0 = fmaxf(m0, cm0);
        const float mn1 = fmaxf(m1, cm1);
        const float al0 = ex2(m0 - mn0);
        const float al1 = ex2(m1 - mn1);
        float sum0 = 0.0f, sum1 = 0.0f;
#pragma unroll
        for (int nf = 0; nf < 8; nf++) {
            s[nf][0] = ex2(s[nf][0] - mn0); sum0 += s[nf][0];
            s[nf][1] = ex2(s[nf][1] - mn0); sum0 += s[nf][1];
            s[nf][2] = ex2(s[nf][2] - mn1); sum1 += s[nf][2];
            s[nf][3] = ex2(s[nf][3] - mn1); sum1 += s[nf][3];
        }
        sum0 += __shfl_xor_sync(0xFFFFFFFFu, sum0, 1);
        sum0 += __shfl_xor_sync(0xFFFFFFFFu, sum0, 2);
        sum1 += __shfl_xor_sync(0xFFFFFFFFu, sum1, 1);
        sum1 += __shfl_xor_sync(0xFFFFFFFFu, sum1, 2);
        l0 = l0 * al0 + sum0; m0 = mn0;
        l1 = l1 * al1 + sum1; m1 = mn1;
#pragma unroll
        for (int nf = 0; nf < 8; nf++) {
            o[nf][0] *= al0; o[nf][1] *= al0;
            o[nf][2] *= al1; o[nf][3] *= al1;
        }

        // ---- O += P V (single-term P) ----
#pragma unroll
        for (int kf = 0; kf < 4; kf++) {
            uint32_t ph[4];
            {
                __half2 p0 = __floats2half2_rn(s[2 * kf][0],     s[2 * kf][1]);
                __half2 p1 = __floats2half2_rn(s[2 * kf][2],     s[2 * kf][3]);
                __half2 p2 = __floats2half2_rn(s[2 * kf + 1][0], s[2 * kf + 1][1]);
                __half2 p3 = __floats2half2_rn(s[2 * kf + 1][2], s[2 * kf + 1][3]);
                ph[0] = *(uint32_t*)&p0; ph[1] = *(uint32_t*)&p1;
                ph[2] = *(uint32_t*)&p2; ph[3] = *(uint32_t*)&p3;
            }
#pragma unroll
            for (int nf = 0; nf < 8; nf++) {
                uint32_t v0, v1;
                const int vrow = kf * 16 + lh * 8 + l8;
                ldsm_x2_t(v0, v1, stg + KVTILE + (uint32_t)(vrow * 128)
                          + (uint32_t)(((nf ^ l8)) << 4));
                mma_f16(o[nf], ph[0], ph[1], ph[2], ph[3], v0, v1);
            }
        }

        if (c + 1 < NC) cp_wait<0>();
        __syncthreads();
    }

    // ---- normalize and write single fp16 ----
    const float inv0 = 1.0f / l0;
    const float inv1 = 1.0f / l1;
    const int row0 = qt * 128 + wid * 16 + g;
#pragma unroll
    for (int nf = 0; nf < 8; nf++) {
        const int col = h * DD + nf * 8 + 2 * t4;
        const size_t a0 = (size_t)(b * NN + row0) * CDIM + col;
        const size_t a1 = (size_t)(b * NN + row0 + 8) * CDIM + col;
        __half2 v0 = __floats2half2_rn(o[nf][0] * inv0, o[nf][1] * inv0);
        __half2 v1 = __floats2half2_rn(o[nf][2] * inv1, o[nf][3] * inv1);
        *(uint32_t*)&O1[a0] = *(uint32_t*)&v0;
        *(uint32_t*)&O1[a1] = *(uint32_t*)&v1;
    }
#undef ISSUE_KV
}

// ---------------------------------------------------------------------------
// Launch
// ---------------------------------------------------------------------------
extern "C" void kernel_launch(void* const* d_in, const int* in_sizes, int n_in,
                              void* d_out, int out_size)
{
    const float* x  = (const float*)d_in[0];
    const float* y  = (const float*)d_in[1];
    const float* Wq = (const float*)d_in[2];
    const float* Wk = (const float*)d_in[3];
    const float* Wv = (const float*)d_in[4];
    const float* Wp = (const float*)d_in[5];
    const float* bp = (const float*)d_in[6];
    float* out = (float*)d_out;

    __half *xh, *xl, *y1, *w, *q1, *k1, *v1, *ao;
    float* po;
    cudaGetSymbolAddress((void**)&xh, g_xh);   cudaGetSymbolAddress((void**)&xl, g_xl);
    cudaGetSymbolAddress((void**)&y1, g_y1);
    cudaGetSymbolAddress((void**)&w,  g_w);
    cudaGetSymbolAddress((void**)&q1, g_q1);
    cudaGetSymbolAddress((void**)&k1, g_k1);   cudaGetSymbolAddress((void**)&v1, g_v1);
    cudaGetSymbolAddress((void**)&ao, g_ao);
    cudaGetSymbolAddress((void**)&po, g_po);

    cudaFuncSetAttribute(proj_fused,  cudaFuncAttributeMaxDynamicSharedMemorySize, GEMM_SMEM);
    cudaFuncSetAttribute(gemm_out_sk, cudaFuncAttributeMaxDynamicSharedMemorySize, 2 * 2 * GTILE);
    cudaFuncSetAttribute(attn_mma,    cudaFuncAttributeMaxDynamicSharedMemorySize, ATTN_SMEM);

    float* p0 = po;
    float* p1 = po + BB * NN * CDIM;

    // 1. Fused convert
    convert_all<<<(TOT4 + 255) / 256, 256>>>(x, y, Wq, Wk, Wv, Wp, xh, xl, y1, w);

    // 2. Fused Q/K/V projections
    proj_fused<<<dim3(CDIM / 128, (BB * LLEN) / 128, 3), 256, GEMM_SMEM>>>(
        xh, xl, y1, w, q1, k1, v1);

    // 3. Flash attention (all-single fp16) -> single fp16
    attn_mma<<<dim3(NN / 128, HH, BB), 256, ATTN_SMEM>>>(ao, q1, k1, v1);

    // 4. Output projection, split-K=2 (single-term A)
    gemm_out_sk<<<dim3(CDIM / 128, (BB * NN) / 128, 2), 256, 2 * 2 * GTILE>>>(
        p0, p1, ao, w + 3 * (size_t)CDIM * CDIM);

    // 5. Merge partials + bias
    merge_out<<<((BB * NN * CDIM / 4) + 255) / 256, 256>>>(out, p0, p1, bp);
}

// round 17
// speedup vs baseline: 1.8617x; 1.0457x over previous
#include <cuda_runtime.h>
#include <cuda_fp16.h>
#include <math.h>
#include <stdint.h>

// Problem shape (fixed by the dataset)
#define BB   2
#define NN   1024
#define LLEN 4096
#define CDIM 1024
#define HH   16
#define DD   64

// ---------------- scratch (device globals; no allocs allowed) ---------------
__device__ __half g_x1[BB * NN * CDIM];                    // single fp16
__device__ __half g_y1[BB * LLEN * CDIM];                  // single fp16
__device__ __half g_w[4 * CDIM * CDIM];                    // single fp16 weights
__device__ __half g_q1[BB * NN * CDIM];                    // single fp16, pre-scaled
__device__ __half g_k1[BB * LLEN * CDIM];                  // single fp16
__device__ __half g_v1[BB * LLEN * CDIM];                  // single fp16
__device__ __half g_ao[BB * NN * CDIM];                    // single fp16
__device__ float  g_po[2][BB * NN * CDIM];                 // split-K partials

extern __shared__ char dsm[];

// ---------------------------------------------------------------------------
// helpers
// ---------------------------------------------------------------------------
static __device__ __forceinline__ uint32_t smem_u32(const void* p) {
    uint32_t a;
    asm("{ .reg .u64 t; cvta.to.shared.u64 t, %1; cvt.u32.u64 %0, t; }"
        : "=r"(a) : "l"(p));
    return a;
}
static __device__ __forceinline__ void cp16(uint32_t dst, const void* src) {
    asm volatile("cp.async.cg.shared.global [%0], [%1], 16;"
                 :: "r"(dst), "l"(src));
}
static __device__ __forceinline__ void cp_commit() {
    asm volatile("cp.async.commit_group;" ::: "memory");
}
template <int N_>
static __device__ __forceinline__ void cp_wait() {
    asm volatile("cp.async.wait_group %0;" :: "n"(N_) : "memory");
}
// fast 2^x via MUFU
static __device__ __forceinline__ float ex2(float x) {
    float y;
    asm("ex2.approx.ftz.f32 %0, %1;" : "=f"(y) : "f"(x));
    return y;
}
static __device__ __forceinline__ void mma_f16(
    float* c, uint32_t a0, uint32_t a1, uint32_t a2, uint32_t a3,
    uint32_t b0, uint32_t b1)
{
    asm volatile(
        "mma.sync.aligned.m16n8k16.row.col.f32.f16.f16.f32 "
        "{%0,%1,%2,%3}, {%4,%5,%6,%7}, {%8,%9}, {%0,%1,%2,%3};"
        : "+f"(c[0]), "+f"(c[1]), "+f"(c[2]), "+f"(c[3])
        : "r"(a0), "r"(a1), "r"(a2), "r"(a3), "r"(b0), "r"(b1));
}
static __device__ __forceinline__ void ldsm_x4(uint32_t* r, uint32_t addr) {
    asm volatile("ldmatrix.sync.aligned.m8n8.x4.shared.b16 {%0,%1,%2,%3}, [%4];"
                 : "=r"(r[0]), "=r"(r[1]), "=r"(r[2]), "=r"(r[3]) : "r"(addr));
}
static __device__ __forceinline__ void ldsm_x2_t(uint32_t& r0, uint32_t& r1, uint32_t addr) {
    asm volatile("ldmatrix.sync.aligned.m8n8.x2.trans.shared.b16 {%0,%1}, [%2];"
                 : "=r"(r0), "=r"(r1) : "r"(addr));
}

// ---------------------------------------------------------------------------
// fused convert: x, y, Wq..Wp -> single fp16.  ONE launch.
// ---------------------------------------------------------------------------
#define X4 ((BB * NN * CDIM) / 4)
#define Y4 ((BB * LLEN * CDIM) / 4)
#define W4 ((CDIM * CDIM) / 4)
#define TOT4 (X4 + Y4 + 4 * W4)

__global__ void convert_all(const float* __restrict__ x, const float* __restrict__ y,
                            const float* __restrict__ Wq, const float* __restrict__ Wk,
                            const float* __restrict__ Wv, const float* __restrict__ Wp,
                            __half* __restrict__ x1, __half* __restrict__ y1,
                            __half* __restrict__ w)
{
    const int i = blockIdx.x * blockDim.x + threadIdx.x;
    if (i >= TOT4) return;

    const float* src; __half* dst; int j;
    if (i < X4)           { src = x; dst = x1; j = i; }
    else if (i < X4 + Y4) { src = y; dst = y1; j = i - X4; }
    else {
        int r = i - X4 - Y4;
        const int wsel = r / W4;
        j = r - wsel * W4;
        src = (wsel == 0) ? Wq : (wsel == 1) ? Wk : (wsel == 2) ? Wv : Wp;
        dst = w + (size_t)wsel * CDIM * CDIM;
    }
    float4 v = ((const float4*)src)[j];
    __half2 a = __floats2half2_rn(v.x, v.y);
    __half2 b = __floats2half2_rn(v.z, v.w);
    ((uint32_t*)dst)[j * 2 + 0] = *(uint32_t*)&a;
    ((uint32_t*)dst)[j * 2 + 1] = *(uint32_t*)&b;
}

// ---------------------------------------------------------------------------
// GEMM body, fp16 single x single: C = A * B^T.
// BK=64, tile 128x128, 256 thr.  Smem row 128B, swizzle s^(r&7).
// omode: 0 = fp32 C, 2 = fp16 single (*oscale).
// ---------------------------------------------------------------------------
#define GTILE  16384
#define STB    (2 * GTILE)
#define GEMM_SMEM (2 * STB)            // 65536

#define LOAD_STAGE(cc, buf) do {                                              \
        const uint32_t bo = (uint32_t)(buf) * STB;                            \
        _Pragma("unroll")                                                     \
        for (int k = 0; k < 4; k++) {                                         \
            const int j   = tid + k * 256;                                    \
            const int row = j >> 3;                                           \
            const int s   = j & 7;                                            \
            const uint32_t doff = (uint32_t)(row * 128 + (((s) ^ (row & 7)) << 4)); \
            cp16(sb + bo + doff,         As + (size_t)(m0 + row) * K + (cc) * 64 + s * 8); \
            cp16(sb + bo + GTILE + doff, Bs + (size_t)(n0 + row) * K + (cc) * 64 + s * 8); \
        }                                                                     \
    } while (0)

static __device__ __forceinline__ void gemm_body(
    float* __restrict__ C, __half* __restrict__ Cs,
    const __half* __restrict__ As, const __half* __restrict__ Bs,
    float oscale, int omode, int N, int K, int bx, int by, int c0, int c1)
{
    const int tid  = threadIdx.x;
    const int wid  = tid >> 5;
    const int lane = tid & 31;
    const int wm   = wid & 3;
    const int wn   = wid >> 2;
    const int g    = lane >> 2;
    const int t4   = lane & 3;
    const int m0   = by * 128;
    const int n0   = bx * 128;
    const int r15  = lane & 15;
    const int hi8  = lane >> 4;
    const int r7   = r15 & 7;

    const uint32_t sb = smem_u32(dsm);

    float acc[2][8][4];
#pragma unroll
    for (int mf = 0; mf < 2; mf++)
#pragma unroll
        for (int nf = 0; nf < 8; nf++)
#pragma unroll
            for (int j = 0; j < 4; j++) acc[mf][nf][j] = 0.0f;

    LOAD_STAGE(c0, 0);
    cp_commit();

    for (int c = c0; c < c1; c++) {
        const int buf = (c - c0) & 1;
        if (c + 1 < c1) {
            LOAD_STAGE(c + 1, buf ^ 1);
            cp_commit();
            cp_wait<1>();
        } else {
            cp_wait<0>();
        }
        __syncthreads();

        const uint32_t stg = sb + (uint32_t)buf * STB;

#pragma unroll
        for (int ks = 0; ks < 4; ks++) {
            const uint32_t sx = (uint32_t)((((2 * ks + hi8) ^ r7)) << 4);
            uint32_t a4[2][4];
#pragma unroll
            for (int mf = 0; mf < 2; mf++)
                ldsm_x4(a4[mf], stg + (uint32_t)((wm * 32 + mf * 16 + r15) * 128) + sx);
#pragma unroll
            for (int nfp = 0; nfp < 4; nfp++) {
                uint32_t b4[4];
                ldsm_x4(b4, stg + GTILE +
                        (uint32_t)((wn * 64 + nfp * 16 + r15) * 128) + sx);
#pragma unroll
                for (int mf = 0; mf < 2; mf++) {
                    mma_f16(acc[mf][2 * nfp],     a4[mf][0], a4[mf][1], a4[mf][2], a4[mf][3], b4[0], b4[2]);
                    mma_f16(acc[mf][2 * nfp + 1], a4[mf][0], a4[mf][1], a4[mf][2], a4[mf][3], b4[1], b4[3]);
                }
            }
        }
        __syncthreads();
    }

#pragma unroll
    for (int mf = 0; mf < 2; mf++) {
        const int row = m0 + wm * 32 + mf * 16 + g;
#pragma unroll
        for (int nf = 0; nf < 8; nf++) {
            const int col = n0 + wn * 64 + nf * 8 + 2 * t4;
            if (omode == 0) {
                float2 v0, v1;
                v0.x = acc[mf][nf][0]; v0.y = acc[mf][nf][1];
                v1.x = acc[mf][nf][2]; v1.y = acc[mf][nf][3];
                *(float2*)&C[(size_t)row * N + col]       = v0;
                *(float2*)&C[(size_t)(row + 8) * N + col] = v1;
            } else {
                __half2 v0 = __floats2half2_rn(acc[mf][nf][0] * oscale,
                                               acc[mf][nf][1] * oscale);
                __half2 v1 = __floats2half2_rn(acc[mf][nf][2] * oscale,
                                               acc[mf][nf][3] * oscale);
                *(uint32_t*)&Cs[(size_t)row * N + col]       = *(uint32_t*)&v0;
                *(uint32_t*)&Cs[(size_t)(row + 8) * N + col] = *(uint32_t*)&v1;
            }
        }
    }
}

// Fused Q/K/V projection (z = 0:Q (pre-scaled out), 1:K, 2:V; all single)
#define QSCALE (0.125f * 1.44269504f)

__global__ __launch_bounds__(256, 2)
void proj_fused(const __half* __restrict__ x1, const __half* __restrict__ y1,
                const __half* __restrict__ w,
                __half* __restrict__ q1, __half* __restrict__ k1,
                __half* __restrict__ v1)
{
    const int z = blockIdx.z;
    if (z == 0 && blockIdx.y >= (BB * NN) / 128) return;

    const __half* As = (z == 0) ? x1 : y1;
    const __half* Bs = w + (size_t)z * CDIM * CDIM;
    __half* Cs = (z == 0) ? q1 : (z == 1) ? k1 : v1;
    const float oscale = (z == 0) ? QSCALE : 1.0f;

    gemm_body(nullptr, Cs, As, Bs, oscale, 2,
              CDIM, CDIM, blockIdx.x, blockIdx.y, 0, CDIM >> 6);
}

// Output projection, split-K=2
__global__ __launch_bounds__(256, 2)
void gemm_out_sk(float* __restrict__ P0, float* __restrict__ P1,
                 const __half* __restrict__ A1, const __half* __restrict__ Bs)
{
    const int z = blockIdx.z;
    const int half = (CDIM >> 6) / 2;
    gemm_body(z ? P1 : P0, nullptr, A1, Bs, 1.0f, 0,
              CDIM, CDIM, blockIdx.x, blockIdx.y, z * half, (z + 1) * half);
}

// merge: out = p0 + p1 + bias
__global__ void merge_out(float* __restrict__ out,
                          const float* __restrict__ p0, const float* __restrict__ p1,
                          const float* __restrict__ bias)
{
    const int i = blockIdx.x * blockDim.x + threadIdx.x;
    if (i >= (BB * NN * CDIM) / 4) return;
    const int col4 = i & (CDIM / 4 - 1);
    float4 a = ((const float4*)p0)[i];
    float4 b = ((const float4*)p1)[i];
    float4 bb = ((const float4*)bias)[col4];
    float4 o;
    o.x = a.x + b.x + bb.x; o.y = a.y + b.y + bb.y;
    o.z = a.z + b.z + bb.z; o.w = a.w + b.w + bb.w;
    ((float4*)out)[i] = o;
}

// ---------------------------------------------------------------------------
// Flash attention: all-single fp16, base-2 softmax via ex2.approx.
// CTA = 128 queries of one (b,h); 8 warps x 16 rows, warp-local softmax.
// Q single persistent in smem (16KB); K, V single fp16, double-buffered.
// ---------------------------------------------------------------------------
#define QSM_B   16384
#define KVTILE  8192
#define ASTAGE_B (2 * KVTILE)
#define ATTN_SMEM (QSM_B + 2 * ASTAGE_B)   // 49152

__global__ __launch_bounds__(256, 2)
void attn_mma(__half* __restrict__ O1,
              const __half* __restrict__ Q1,
              const __half* __restrict__ K1, const __half* __restrict__ V1)
{
    const int tid  = threadIdx.x;
    const int wid  = tid >> 5;
    const int lane = tid & 31;
    const int g    = lane >> 2;
    const int t4   = lane & 3;
    const int r15  = lane & 15;
    const int hi8  = lane >> 4;
    const int r7   = r15 & 7;
    const int l8   = lane & 7;
    const int lh   = (lane >> 3) & 1;
    const int qt   = blockIdx.x;
    const int h    = blockIdx.y;
    const int b    = blockIdx.z;
    const uint32_t sb = smem_u32(dsm);

    // ---- stage Q (single) into persistent smem ----
    {
#pragma unroll
        for (int k = 0; k < 4; k++) {
            const int j   = tid + k * 256;
            const int row = j >> 3;
            const int s   = j & 7;
            const __half* src = Q1 +
                ((size_t)(b * NN + qt * 128 + row) * CDIM + h * DD + s * 8);
            cp16(sb + row * 128 + ((s ^ (row & 7)) << 4), src);
        }
        cp_commit();
    }

    const size_t kbase = (size_t)b * LLEN * CDIM + h * DD;

#define ISSUE_KV(cc, buf) do {                                                \
        _Pragma("unroll")                                                     \
        for (int k = 0; k < 4; k++) {                                         \
            const int j    = tid + k * 256;                                   \
            const int tile = j >> 9;                                          \
            const int rem  = j & 511;                                         \
            const int row  = rem >> 3;                                        \
            const int s    = rem & 7;                                         \
            const __half* src = (tile ? V1 : K1) + kbase +                    \
                (size_t)((cc) * 64 + row) * CDIM + s * 8;                     \
            cp16(sb + QSM_B + (buf) * ASTAGE_B + tile * KVTILE                \
                 + row * 128 + ((s ^ (row & 7)) << 4), src);                  \
        }                                                                     \
    } while (0)

    float m0 = -1e30f, m1 = -1e30f, l0 = 0.0f, l1 = 0.0f;
    float o[8][4];
#pragma unroll
    for (int nf = 0; nf < 8; nf++)
#pragma unroll
        for (int j = 0; j < 4; j++) o[nf][j] = 0.0f;

    ISSUE_KV(0, 0); cp_commit();
    cp_wait<0>(); __syncthreads();

    const uint32_t qrow = (uint32_t)((wid * 16 + r15) * 128);

    const int NC = LLEN / 64;
    for (int c = 0; c < NC; c++) {
        const int buf = c & 1;
        if (c + 1 < NC) { ISSUE_KV(c + 1, buf ^ 1); cp_commit(); }

        const uint32_t stg = sb + QSM_B + buf * ASTAGE_B;

        // ---- S (base-2 logits) = Q K^T ----
        float s[8][4];
#pragma unroll
        for (int nf = 0; nf < 8; nf++)
#pragma unroll
            for (int j = 0; j < 4; j++) s[nf][j] = 0.0f;

#pragma unroll
        for (int kf = 0; kf < 4; kf++) {
            const uint32_t sx = (uint32_t)((((2 * kf + hi8) ^ r7)) << 4);
            uint32_t q4[4];
            ldsm_x4(q4, sb + qrow + sx);
#pragma unroll
            for (int nfp = 0; nfp < 4; nfp++) {
                uint32_t k4[4];
                ldsm_x4(k4, stg + (uint32_t)((nfp * 16 + r15) * 128) + sx);
                mma_f16(s[2 * nfp],     q4[0], q4[1], q4[2], q4[3], k4[0], k4[2]);
                mma_f16(s[2 * nfp + 1], q4[0], q4[1], q4[2], q4[3], k4[1], k4[3]);
            }
        }

        // ---- online softmax, base-2 via ex2.approx (rows g and g+8) ----
        float cm0 = -1e30f, cm1 = -1e30f;
#pragma unroll
        for (int nf = 0; nf < 8; nf++) {
            cm0 = fmaxf(cm0, fmaxf(s[nf][0], s[nf][1]));
            cm1 = fmaxf(cm1, fmaxf(s[nf][2], s[nf][3]));
        }
        cm0 = fmaxf(cm0, __shfl_xor_sync(0xFFFFFFFFu, cm0, 1));
        cm0 = fmaxf(cm0, __shfl_xor_sync(0xFFFFFFFFu, cm0, 2));
        cm1 = fmaxf(cm1, __shfl_xor_sync(0xFFFFFFFFu, cm1, 1));
        cm1 = fmaxf(cm1, __shfl_xor_sync(0xFFFFFFFFu, cm1, 2));
        const float mn0 = fmaxf(m0, cm0);
        const float mn1 = fmaxf(m1, cm1);
        const float al0 = ex2(m0 - mn0);
        const float al1 = ex2(m1 - mn1);
        float sum0 = 0.0f, sum1 = 0.0f;
#pragma unroll
        for (int nf = 0; nf < 8; nf++) {
            s[nf][0] = ex2(s[nf][0] - mn0); sum0 += s[nf][0];
            s[nf][1] = ex2(s[nf][1] - mn0); sum0 += s[nf][1];
            s[nf][2] = ex2(s[nf][2] - mn1); sum1 += s[nf][2];
            s[nf][3] = ex2(s[nf][3] - mn1); sum1 += s[nf][3];
        }
        sum0 += __shfl_xor_sync(0xFFFFFFFFu, sum0, 1);
        sum0 += __shfl_xor_sync(0xFFFFFFFFu, sum0, 2);
        sum1 += __shfl_xor_sync(0xFFFFFFFFu, sum1, 1);
        sum1 += __shfl_xor_sync(0xFFFFFFFFu, sum1, 2);
        l0 = l0 * al0 + sum0; m0 = mn0;
        l1 = l1 * al1 + sum1; m1 = mn1;
#pragma unroll
        for (int nf = 0; nf < 8; nf++) {
            o[nf][0] *= al0; o[nf][1] *= al0;
            o[nf][2] *= al1; o[nf][3] *= al1;
        }

        // ---- O += P V ----
#pragma unroll
        for (int kf = 0; kf < 4; kf++) {
            uint32_t ph[4];
            {
                __half2 p0 = __floats2half2_rn(s[2 * kf][0],     s[2 * kf][1]);
                __half2 p1 = __floats2half2_rn(s[2 * kf][2],     s[2 * kf][3]);
                __half2 p2 = __floats2half2_rn(s[2 * kf + 1][0], s[2 * kf + 1][1]);
                __half2 p3 = __floats2half2_rn(s[2 * kf + 1][2], s[2 * kf + 1][3]);
                ph[0] = *(uint32_t*)&p0; ph[1] = *(uint32_t*)&p1;
                ph[2] = *(uint32_t*)&p2; ph[3] = *(uint32_t*)&p3;
            }
#pragma unroll
            for (int nf = 0; nf < 8; nf++) {
                uint32_t v0, v1;
                const int vrow = kf * 16 + lh * 8 + l8;
                ldsm_x2_t(v0, v1, stg + KVTILE + (uint32_t)(vrow * 128)
                          + (uint32_t)(((nf ^ l8)) << 4));
                mma_f16(o[nf], ph[0], ph[1], ph[2], ph[3], v0, v1);
            }
        }

        if (c + 1 < NC) cp_wait<0>();
        __syncthreads();
    }

    // ---- normalize and write single fp16 ----
    const float inv0 = 1.0f / l0;
    const float inv1 = 1.0f / l1;
    const int row0 = qt * 128 + wid * 16 + g;
#pragma unroll
    for (int nf = 0; nf < 8; nf++) {
        const int col = h * DD + nf * 8 + 2 * t4;
        const size_t a0 = (size_t)(b * NN + row0) * CDIM + col;
        const size_t a1 = (size_t)(b * NN + row0 + 8) * CDIM + col;
        __half2 v0 = __floats2half2_rn(o[nf][0] * inv0, o[nf][1] * inv0);
        __half2 v1 = __floats2half2_rn(o[nf][2] * inv1, o[nf][3] * inv1);
        *(uint32_t*)&O1[a0] = *(uint32_t*)&v0;
        *(uint32_t*)&O1[a1] = *(uint32_t*)&v1;
    }
#undef ISSUE_KV
}

// ---------------------------------------------------------------------------
// Launch
// ---------------------------------------------------------------------------
extern "C" void kernel_launch(void* const* d_in, const int* in_sizes, int n_in,
                              void* d_out, int out_size)
{
    const float* x  = (const float*)d_in[0];
    const float* y  = (const float*)d_in[1];
    const float* Wq = (const float*)d_in[2];
    const float* Wk = (const float*)d_in[3];
    const float* Wv = (const float*)d_in[4];
    const float* Wp = (const float*)d_in[5];
    const float* bp = (const float*)d_in[6];
    float* out = (float*)d_out;

    __half *x1, *y1, *w, *q1, *k1, *v1, *ao;
    float* po;
    cudaGetSymbolAddress((void**)&x1, g_x1);
    cudaGetSymbolAddress((void**)&y1, g_y1);
    cudaGetSymbolAddress((void**)&w,  g_w);
    cudaGetSymbolAddress((void**)&q1, g_q1);
    cudaGetSymbolAddress((void**)&k1, g_k1);
    cudaGetSymbolAddress((void**)&v1, g_v1);
    cudaGetSymbolAddress((void**)&ao, g_ao);
    cudaGetSymbolAddress((void**)&po, g_po);

    cudaFuncSetAttribute(proj_fused,  cudaFuncAttributeMaxDynamicSharedMemorySize, GEMM_SMEM);
    cudaFuncSetAttribute(gemm_out_sk, cudaFuncAttributeMaxDynamicSharedMemorySize, GEMM_SMEM);
    cudaFuncSetAttribute(attn_mma,    cudaFuncAttributeMaxDynamicSharedMemorySize, ATTN_SMEM);

    float* p0 = po;
    float* p1 = po + BB * NN * CDIM;

    // 1. Fused convert (all single fp16)
    convert_all<<<(TOT4 + 255) / 256, 256>>>(x, y, Wq, Wk, Wv, Wp, x1, y1, w);

    // 2. Fused Q/K/V projections (all single x single)
    proj_fused<<<dim3(CDIM / 128, (BB * LLEN) / 128, 3), 256, GEMM_SMEM>>>(
        x1, y1, w, q1, k1, v1);

    // 3. Flash attention (all-single fp16) -> single fp16
    attn_mma<<<dim3(NN / 128, HH, BB), 256, ATTN_SMEM>>>(ao, q1, k1, v1);

    // 4. Output projection, split-K=2
    gemm_out_sk<<<dim3(CDIM / 128, (BB * NN) / 128, 2), 256, GEMM_SMEM>>>(
        p0, p1, ao, w + 3 * (size_t)CDIM * CDIM);

    // 5. Merge partials + bias
    merge_out<<<((BB * NN * CDIM / 4) + 255) / 256, 256>>>(out, p0, p1, bp);
}